// round 6
// baseline (speedup 1.0000x reference)
#include <cuda_runtime.h>

// Problem-fixed maxima (from setup_inputs): N=100000, E=1600000, d_out<=32.
#define MAXN 100000
#define MAXD 32

// Scratch (device globals — allocation-free per harness rules)
__device__ float g_Z[MAXN * MAXD];    // per-layer transformed features z = hW
__device__ float g_AGG[MAXN * MAXD];  // unnormalized aggregation  sum_e w*z[src]
__device__ float g_H[MAXN * MAXD];    // layer output (input to next layer)
__device__ float g_SS[MAXN];          // s_src per node
__device__ float g_SD[MAXN];          // s_dst per node
__device__ float g_DEN[MAXN];         // sum_e w  per dst node

// ---------------------------------------------------------------------------
// Node pass: z = h @ W, s_src = z . a[:d], s_dst = z . a[d:], and zero AGG/DEN.
// One warp per node. W and a cached in shared; h row staged per-warp in shared.
// ---------------------------------------------------------------------------
__global__ void node_gemm_kernel(const float* __restrict__ hext, int use_ext,
                                 const float* __restrict__ W,
                                 const float* __restrict__ a,
                                 int N, int din, int dout)
{
    extern __shared__ float sh[];
    float* Ws = sh;                    // din*dout
    float* as = Ws + din * dout;       // 2*dout
    float* hs = as + 2 * dout;         // warpsPerBlock * din

    int tid = threadIdx.x;
    for (int i = tid; i < din * dout; i += blockDim.x) Ws[i] = W[i];
    for (int i = tid; i < 2 * dout; i += blockDim.x) as[i] = a[i];
    __syncthreads();

    int lane = tid & 31;
    int wrp  = tid >> 5;
    int warpsPerBlock = blockDim.x >> 5;
    float* hw = hs + wrp * din;

    for (int n = blockIdx.x * warpsPerBlock + wrp; n < N;
         n += gridDim.x * warpsPerBlock)
    {
        // stage h row
        const float* hrow = use_ext ? (hext + (long long)n * din)
                                    : (g_H + (long long)n * din);
        for (int k = lane; k < din; k += 32) hw[k] = hrow[k];
        __syncwarp();

        float z = 0.f;
        if (lane < dout) {
            #pragma unroll 4
            for (int k = 0; k < din; k++) z += hw[k] * Ws[k * dout + lane];
            g_Z[n * dout + lane]   = z;
            g_AGG[n * dout + lane] = 0.f;
        }
        float ps = (lane < dout) ? z * as[lane] : 0.f;
        float pd = (lane < dout) ? z * as[dout + lane] : 0.f;
        #pragma unroll
        for (int o = 16; o; o >>= 1) {
            ps += __shfl_down_sync(0xffffffffu, ps, o);
            pd += __shfl_down_sync(0xffffffffu, pd, o);
        }
        if (lane == 0) { g_SS[n] = ps; g_SD[n] = pd; g_DEN[n] = 0.f; }
        __syncwarp();
    }
}

// ---------------------------------------------------------------------------
// Edge pass, d_out == 32: one warp per edge. Lane j handles feature j.
// Accumulates AGG[dst][:] += w * Z[src][:], DEN[dst] += w.
// (Softmax max-shift dropped — shift-invariant, and |e| <= ~5 here.)
// ---------------------------------------------------------------------------
__global__ void edge_pass32_kernel(const int* __restrict__ src,
                                   const int* __restrict__ dst, int E)
{
    int lane = threadIdx.x & 31;
    long long gwarp = (long long)(blockIdx.x) * (blockDim.x >> 5) + (threadIdx.x >> 5);
    if (gwarp >= E) return;
    int e = (int)gwarp;

    int s = __ldg(src + e);
    int d = __ldg(dst + e);
    float w;
    if (lane == 0) {
        float x = g_SS[s] + g_SD[d];
        x = (x > 0.f) ? x : 0.01f * x;   // leaky_relu
        w = __expf(x);
        atomicAdd(g_DEN + d, w);
    }
    w = __shfl_sync(0xffffffffu, w, 0);
    float val = w * g_Z[s * 32 + lane];
    atomicAdd(g_AGG + d * 32 + lane, val);
}

// ---------------------------------------------------------------------------
// Edge pass, d_out == 1: one thread per edge.
// ---------------------------------------------------------------------------
__global__ void edge_pass1_kernel(const int* __restrict__ src,
                                  const int* __restrict__ dst, int E)
{
    int e = blockIdx.x * blockDim.x + threadIdx.x;
    if (e >= E) return;
    int s = __ldg(src + e);
    int d = __ldg(dst + e);
    float x = g_SS[s] + g_SD[d];
    x = (x > 0.f) ? x : 0.01f * x;
    float w = __expf(x);
    atomicAdd(g_DEN + d, w);
    atomicAdd(g_AGG + d, w * g_Z[s]);
}

// ---------------------------------------------------------------------------
// Finalize: out = act(AGG / max(DEN, 1e-9)).  mode 0 -> relu into g_H,
// mode 1 -> sigmoid into external output.
// ---------------------------------------------------------------------------
__global__ void finalize_kernel(int N, int dout, int mode, float* __restrict__ outext)
{
    int i = blockIdx.x * blockDim.x + threadIdx.x;
    if (i >= N * dout) return;
    int n = i / dout;
    float v = g_AGG[i] / fmaxf(g_DEN[n], 1e-9f);
    if (mode == 0) {
        g_H[i] = fmaxf(v, 0.f);
    } else {
        outext[i] = 1.f / (1.f + __expf(-v));
    }
}

// ---------------------------------------------------------------------------
extern "C" void kernel_launch(void* const* d_in, const int* in_sizes, int n_in,
                              void* d_out, int out_size)
{
    const float* feat = (const float*)d_in[0];
    const int*   src  = (const int*)d_in[1];
    const int*   dst  = (const int*)d_in[2];
    const float* W1   = (const float*)d_in[3];
    const float* a1   = (const float*)d_in[4];
    const float* W2   = (const float*)d_in[5];
    const float* a2   = (const float*)d_in[6];
    const float* W3   = (const float*)d_in[7];
    const float* a3   = (const float*)d_in[8];

    const int E   = in_sizes[1];
    const int d1  = in_sizes[4] / 2;          // 32
    const int din1 = in_sizes[3] / d1;        // 128
    const int N   = in_sizes[0] / din1;       // 100000
    const int d2  = in_sizes[6] / 2;          // 32
    const int din2 = in_sizes[5] / d2;        // 32
    const int d3  = in_sizes[8] / 2;          // 1
    const int din3 = in_sizes[7] / d3;        // 32

    const int NT = 256;
    const int WPB = NT / 32;
    const int nodeBlocks = (N + WPB - 1) / WPB;
    const int edgeWarpBlocks = (E + WPB - 1) / WPB;      // one warp per edge
    const int edgeThrBlocks  = (E + NT - 1) / NT;

    float* out = (float*)d_out;

    // ---- Layer 1 (din=128, dout=32), relu ----
    {
        size_t shm = (size_t)(din1 * d1 + 2 * d1 + WPB * din1) * sizeof(float);
        node_gemm_kernel<<<nodeBlocks, NT, shm>>>(feat, 1, W1, a1, N, din1, d1);
        edge_pass32_kernel<<<edgeWarpBlocks, NT>>>(src, dst, E);
        finalize_kernel<<<(N * d1 + NT - 1) / NT, NT>>>(N, d1, 0, nullptr);
    }
    // ---- Layer 2 (din=32, dout=32), relu ----
    {
        size_t shm = (size_t)(din2 * d2 + 2 * d2 + WPB * din2) * sizeof(float);
        node_gemm_kernel<<<nodeBlocks, NT, shm>>>(nullptr, 0, W2, a2, N, din2, d2);
        edge_pass32_kernel<<<edgeWarpBlocks, NT>>>(src, dst, E);
        finalize_kernel<<<(N * d2 + NT - 1) / NT, NT>>>(N, d2, 0, nullptr);
    }
    // ---- Layer 3 (din=32, dout=1), sigmoid -> d_out ----
    {
        size_t shm = (size_t)(din3 * d3 + 2 * d3 + WPB * din3) * sizeof(float);
        node_gemm_kernel<<<nodeBlocks, NT, shm>>>(nullptr, 0, W3, a3, N, din3, d3);
        edge_pass1_kernel<<<edgeThrBlocks, NT>>>(src, dst, E);
        finalize_kernel<<<(N * d3 + NT - 1) / NT, NT>>>(N, d3, 1, out);
    }
}

// round 7
// speedup vs baseline: 1.0049x; 1.0049x over previous
#include <cuda_runtime.h>

// Problem-fixed maxima (from setup_inputs): N=100000, E=1600000, d_out<=32.
#define MAXN 100000
#define MAXD 32

// Scratch (device globals — allocation-free per harness rules)
__device__ float g_Z[MAXN * MAXD];    // per-layer transformed features z = hW
__device__ float g_AGG[MAXN * MAXD];  // unnormalized aggregation  sum_e w*z[src]
__device__ float g_H[MAXN * MAXD];    // layer output (input to next layer)
__device__ float g_SS[MAXN];          // s_src per node
__device__ float g_SD[MAXN];          // s_dst per node
__device__ float g_DEN[MAXN];         // sum_e w  per dst node

// ---------------------------------------------------------------------------
// Node pass: z = h @ W, s_src = z . a[:d], s_dst = z . a[d:], and zero AGG/DEN.
// One warp per node. W and a cached in shared; h row staged per-warp in shared.
// ---------------------------------------------------------------------------
__global__ void node_gemm_kernel(const float* __restrict__ hext, int use_ext,
                                 const float* __restrict__ W,
                                 const float* __restrict__ a,
                                 int N, int din, int dout)
{
    extern __shared__ float sh[];
    float* Ws = sh;                    // din*dout
    float* as = Ws + din * dout;       // 2*dout
    float* hs = as + 2 * dout;         // warpsPerBlock * din

    int tid = threadIdx.x;
    for (int i = tid; i < din * dout; i += blockDim.x) Ws[i] = W[i];
    for (int i = tid; i < 2 * dout; i += blockDim.x) as[i] = a[i];
    __syncthreads();

    int lane = tid & 31;
    int wrp  = tid >> 5;
    int warpsPerBlock = blockDim.x >> 5;
    float* hw = hs + wrp * din;

    for (int n = blockIdx.x * warpsPerBlock + wrp; n < N;
         n += gridDim.x * warpsPerBlock)
    {
        // stage h row
        const float* hrow = use_ext ? (hext + (long long)n * din)
                                    : (g_H + (long long)n * din);
        for (int k = lane; k < din; k += 32) hw[k] = hrow[k];
        __syncwarp();

        float z = 0.f;
        if (lane < dout) {
            #pragma unroll 4
            for (int k = 0; k < din; k++) z += hw[k] * Ws[k * dout + lane];
            g_Z[n * dout + lane]   = z;
            g_AGG[n * dout + lane] = 0.f;
        }
        float ps = (lane < dout) ? z * as[lane] : 0.f;
        float pd = (lane < dout) ? z * as[dout + lane] : 0.f;
        #pragma unroll
        for (int o = 16; o; o >>= 1) {
            ps += __shfl_down_sync(0xffffffffu, ps, o);
            pd += __shfl_down_sync(0xffffffffu, pd, o);
        }
        if (lane == 0) { g_SS[n] = ps; g_SD[n] = pd; g_DEN[n] = 0.f; }
        __syncwarp();
    }
}

// ---------------------------------------------------------------------------
// Edge pass, d_out == 32: one warp per edge. Lane j handles feature j.
// Accumulates AGG[dst][:] += w * Z[src][:], DEN[dst] += w.
// (Softmax max-shift dropped — shift-invariant, and |e| <= ~5 here.)
// ---------------------------------------------------------------------------
__global__ void edge_pass32_kernel(const int* __restrict__ src,
                                   const int* __restrict__ dst, int E)
{
    int lane = threadIdx.x & 31;
    long long gwarp = (long long)(blockIdx.x) * (blockDim.x >> 5) + (threadIdx.x >> 5);
    if (gwarp >= E) return;
    int e = (int)gwarp;

    int s = __ldg(src + e);
    int d = __ldg(dst + e);
    float w;
    if (lane == 0) {
        float x = g_SS[s] + g_SD[d];
        x = (x > 0.f) ? x : 0.01f * x;   // leaky_relu
        w = __expf(x);
        atomicAdd(g_DEN + d, w);
    }
    w = __shfl_sync(0xffffffffu, w, 0);
    float val = w * g_Z[s * 32 + lane];
    atomicAdd(g_AGG + d * 32 + lane, val);
}

// ---------------------------------------------------------------------------
// Edge pass, d_out == 1: one thread per edge.
// ---------------------------------------------------------------------------
__global__ void edge_pass1_kernel(const int* __restrict__ src,
                                  const int* __restrict__ dst, int E)
{
    int e = blockIdx.x * blockDim.x + threadIdx.x;
    if (e >= E) return;
    int s = __ldg(src + e);
    int d = __ldg(dst + e);
    float x = g_SS[s] + g_SD[d];
    x = (x > 0.f) ? x : 0.01f * x;
    float w = __expf(x);
    atomicAdd(g_DEN + d, w);
    atomicAdd(g_AGG + d, w * g_Z[s]);
}

// ---------------------------------------------------------------------------
// Finalize: out = act(AGG / max(DEN, 1e-9)).  mode 0 -> relu into g_H,
// mode 1 -> sigmoid into external output.
// ---------------------------------------------------------------------------
__global__ void finalize_kernel(int N, int dout, int mode, float* __restrict__ outext)
{
    int i = blockIdx.x * blockDim.x + threadIdx.x;
    if (i >= N * dout) return;
    int n = i / dout;
    float v = g_AGG[i] / fmaxf(g_DEN[n], 1e-9f);
    if (mode == 0) {
        g_H[i] = fmaxf(v, 0.f);
    } else {
        outext[i] = 1.f / (1.f + __expf(-v));
    }
}

// ---------------------------------------------------------------------------
extern "C" void kernel_launch(void* const* d_in, const int* in_sizes, int n_in,
                              void* d_out, int out_size)
{
    const float* feat = (const float*)d_in[0];
    const int*   src  = (const int*)d_in[1];
    const int*   dst  = (const int*)d_in[2];
    const float* W1   = (const float*)d_in[3];
    const float* a1   = (const float*)d_in[4];
    const float* W2   = (const float*)d_in[5];
    const float* a2   = (const float*)d_in[6];
    const float* W3   = (const float*)d_in[7];
    const float* a3   = (const float*)d_in[8];

    const int E   = in_sizes[1];
    const int d1  = in_sizes[4] / 2;          // 32
    const int din1 = in_sizes[3] / d1;        // 128
    const int N   = in_sizes[0] / din1;       // 100000
    const int d2  = in_sizes[6] / 2;          // 32
    const int din2 = in_sizes[5] / d2;        // 32
    const int d3  = in_sizes[8] / 2;          // 1
    const int din3 = in_sizes[7] / d3;        // 32

    const int NT = 256;
    const int WPB = NT / 32;
    const int nodeBlocks = (N + WPB - 1) / WPB;
    const int edgeWarpBlocks = (E + WPB - 1) / WPB;      // one warp per edge
    const int edgeThrBlocks  = (E + NT - 1) / NT;

    float* out = (float*)d_out;

    // ---- Layer 1 (din=128, dout=32), relu ----
    {
        size_t shm = (size_t)(din1 * d1 + 2 * d1 + WPB * din1) * sizeof(float);
        node_gemm_kernel<<<nodeBlocks, NT, shm>>>(feat, 1, W1, a1, N, din1, d1);
        edge_pass32_kernel<<<edgeWarpBlocks, NT>>>(src, dst, E);
        finalize_kernel<<<(N * d1 + NT - 1) / NT, NT>>>(N, d1, 0, nullptr);
    }
    // ---- Layer 2 (din=32, dout=32), relu ----
    {
        size_t shm = (size_t)(din2 * d2 + 2 * d2 + WPB * din2) * sizeof(float);
        node_gemm_kernel<<<nodeBlocks, NT, shm>>>(nullptr, 0, W2, a2, N, din2, d2);
        edge_pass32_kernel<<<edgeWarpBlocks, NT>>>(src, dst, E);
        finalize_kernel<<<(N * d2 + NT - 1) / NT, NT>>>(N, d2, 0, nullptr);
    }
    // ---- Layer 3 (din=32, dout=1), sigmoid -> d_out ----
    {
        size_t shm = (size_t)(din3 * d3 + 2 * d3 + WPB * din3) * sizeof(float);
        node_gemm_kernel<<<nodeBlocks, NT, shm>>>(nullptr, 0, W3, a3, N, din3, d3);
        edge_pass1_kernel<<<edgeThrBlocks, NT>>>(src, dst, E);
        finalize_kernel<<<(N * d3 + NT - 1) / NT, NT>>>(N, d3, 1, out);
    }
}

// round 8
// speedup vs baseline: 2.1530x; 2.1425x over previous
#include <cuda_runtime.h>

// Problem-fixed maxima (from setup_inputs): N=100000, E=1600000, d_out<=32.
#define MAXN 100000
#define MAXE 1600000
#define MAXD 32
#define SCAN_B 512
#define MAXNB ((MAXN + SCAN_B - 1) / SCAN_B)   // 196

// ---- scratch (device globals; allocation-free per harness rules) ----
__device__ float g_Z[MAXN * MAXD];    // per-layer transformed features z = hW
__device__ float g_H[MAXN * MAXD];    // layer output (input to next layer)
__device__ float g_SS[MAXN];          // s_src per node
__device__ float g_SD[MAXN];          // s_dst per node
__device__ int   g_deg[MAXN];         // in-degree histogram
__device__ int   g_row[MAXN + 1];     // CSR row offsets (by dst)
__device__ int   g_cur[MAXN];         // scatter cursors
__device__ int   g_esrc[MAXE];        // CSR: src node of each dst-sorted edge slot
__device__ int   g_bsum[MAXNB];       // scan block sums

// ===========================================================================
// CSR build (dst-sorted), once per launch
// ===========================================================================
__global__ void zero_deg_kernel(int N)
{
    int i = blockIdx.x * blockDim.x + threadIdx.x;
    if (i < N) g_deg[i] = 0;
}

__global__ void hist_kernel(const int* __restrict__ dst, int E)
{
    int e = blockIdx.x * blockDim.x + threadIdx.x;
    if (e < E) atomicAdd(&g_deg[dst[e]], 1);
}

// per-block exclusive scan of g_deg into g_row, block totals into g_bsum
__global__ void scan1_kernel(int N)
{
    __shared__ int sh[SCAN_B];
    int tid = threadIdx.x;
    int i = blockIdx.x * SCAN_B + tid;
    int v = (i < N) ? g_deg[i] : 0;
    sh[tid] = v;
    __syncthreads();
    #pragma unroll
    for (int o = 1; o < SCAN_B; o <<= 1) {
        int t = (tid >= o) ? sh[tid - o] : 0;
        __syncthreads();
        sh[tid] += t;
        __syncthreads();
    }
    if (i < N) g_row[i] = sh[tid] - v;          // exclusive
    if (tid == SCAN_B - 1) g_bsum[blockIdx.x] = sh[tid];
}

// exclusive scan of block sums (single block)
__global__ void scan2_kernel(int NB)
{
    __shared__ int sh[256];
    int tid = threadIdx.x;
    int v = (tid < NB) ? g_bsum[tid] : 0;
    sh[tid] = v;
    __syncthreads();
    #pragma unroll
    for (int o = 1; o < 256; o <<= 1) {
        int t = (tid >= o) ? sh[tid - o] : 0;
        __syncthreads();
        sh[tid] += t;
        __syncthreads();
    }
    if (tid < NB) g_bsum[tid] = sh[tid] - v;    // exclusive
}

// add block offsets, init cursors, close the row array
__global__ void scan3_kernel(int N, int E)
{
    int i = blockIdx.x * blockDim.x + threadIdx.x;
    if (i < N) {
        int r = g_row[i] + g_bsum[i / SCAN_B];
        g_row[i] = r;
        g_cur[i] = r;
    }
    if (i == 0) g_row[N] = E;
}

__global__ void scatter_kernel(const int* __restrict__ src,
                               const int* __restrict__ dst, int E)
{
    int e = blockIdx.x * blockDim.x + threadIdx.x;
    if (e < E) {
        int p = atomicAdd(&g_cur[dst[e]], 1);
        g_esrc[p] = src[e];
    }
}

// ===========================================================================
// Node pass (generic): z = h@W, s_src, s_dst. One warp per node.
// Used for layer 3 (din=32, dout=1) — tiny.
// ===========================================================================
__global__ void node_gemm_kernel(const float* __restrict__ hext, int use_ext,
                                 const float* __restrict__ W,
                                 const float* __restrict__ a,
                                 int N, int din, int dout)
{
    extern __shared__ float sh[];
    float* Ws = sh;                    // din*dout
    float* as = Ws + din * dout;       // 2*dout
    float* hs = as + 2 * dout;         // warpsPerBlock * din

    int tid = threadIdx.x;
    for (int i = tid; i < din * dout; i += blockDim.x) Ws[i] = W[i];
    for (int i = tid; i < 2 * dout; i += blockDim.x) as[i] = a[i];
    __syncthreads();

    int lane = tid & 31;
    int wrp  = tid >> 5;
    int warpsPerBlock = blockDim.x >> 5;
    float* hw = hs + wrp * din;

    int n = blockIdx.x * warpsPerBlock + wrp;
    if (n >= N) return;

    const float* hrow = use_ext ? (hext + (long long)n * din)
                                : (g_H + (long long)n * din);
    for (int k = lane; k < din; k += 32) hw[k] = hrow[k];
    __syncwarp();

    float z = 0.f;
    if (lane < dout) {
        #pragma unroll 4
        for (int k = 0; k < din; k++) z += hw[k] * Ws[k * dout + lane];
        g_Z[n * dout + lane] = z;
    }
    float ps = (lane < dout) ? z * as[lane] : 0.f;
    float pd = (lane < dout) ? z * as[dout + lane] : 0.f;
    #pragma unroll
    for (int o = 16; o; o >>= 1) {
        ps += __shfl_down_sync(0xffffffffu, ps, o);
        pd += __shfl_down_sync(0xffffffffu, pd, o);
    }
    if (lane == 0) { g_SS[n] = ps; g_SD[n] = pd; }
}

// ===========================================================================
// Node pass, dout==32, 4 nodes per warp (4x smem-W reuse).
// ===========================================================================
__global__ void node_gemm_t4_kernel(const float* __restrict__ hext, int use_ext,
                                    const float* __restrict__ W,
                                    const float* __restrict__ a,
                                    int N, int din)
{
    extern __shared__ float sh[];
    float* Ws = sh;                // din*32
    float* as = Ws + din * 32;     // 64
    float* hs = as + 64;           // WPB * 4 * din

    int tid = threadIdx.x;
    for (int i = tid; i < din * 32; i += blockDim.x) Ws[i] = W[i];
    for (int i = tid; i < 64; i += blockDim.x) as[i] = a[i];
    __syncthreads();

    int lane = tid & 31;
    int wrp  = tid >> 5;
    int WPB  = blockDim.x >> 5;
    float* hw = hs + wrp * 4 * din;

    int n0 = (blockIdx.x * WPB + wrp) * 4;
    if (n0 >= N) return;
    int cnt = (N - n0 < 4) ? (N - n0) : 4;

    for (int t = 0; t < cnt; t++) {
        const float* hr = use_ext ? (hext + (long long)(n0 + t) * din)
                                  : (g_H + (long long)(n0 + t) * din);
        for (int k = lane; k < din; k += 32) hw[t * din + k] = hr[k];
    }
    // zero unused rows so stray inf/nan can't appear (values unused anyway)
    for (int t = cnt; t < 4; t++)
        for (int k = lane; k < din; k += 32) hw[t * din + k] = 0.f;
    __syncwarp();

    float z0 = 0.f, z1 = 0.f, z2 = 0.f, z3 = 0.f;
    #pragma unroll 8
    for (int k = 0; k < din; k++) {
        float wv = Ws[k * 32 + lane];
        z0 = fmaf(hw[k],           wv, z0);
        z1 = fmaf(hw[din + k],     wv, z1);
        z2 = fmaf(hw[2 * din + k], wv, z2);
        z3 = fmaf(hw[3 * din + k], wv, z3);
    }
    float zz[4] = {z0, z1, z2, z3};
    float aS = as[lane], aD = as[32 + lane];
    for (int t = 0; t < cnt; t++) {
        int n = n0 + t;
        g_Z[n * 32 + lane] = zz[t];
        float ps = zz[t] * aS, pd = zz[t] * aD;
        #pragma unroll
        for (int o = 16; o; o >>= 1) {
            ps += __shfl_down_sync(0xffffffffu, ps, o);
            pd += __shfl_down_sync(0xffffffffu, pd, o);
        }
        if (lane == 0) { g_SS[n] = ps; g_SD[n] = pd; }
    }
}

// ===========================================================================
// Gather aggregation, dout==32: one warp per dst node, NO atomics.
// lane j owns feature j. Edge weights computed lane-parallel, broadcast
// via shuffle; z[src] rows read warp-coalesced (128B, L2-resident).
// Fuses softmax-normalize + relu into the epilogue.
// (Softmax max-shift dropped — shift-invariant; |e| small here.)
// ===========================================================================
__global__ void gather32_kernel(int N)
{
    int lane = threadIdx.x & 31;
    int n = blockIdx.x * (blockDim.x >> 5) + (threadIdx.x >> 5);
    if (n >= N) return;

    int beg = g_row[n], end = g_row[n + 1];
    float sd = g_SD[n];
    float acc = 0.f, den = 0.f;

    int base = beg;
    // full 32-edge blocks: unrolled, MLP=4 on the z-row loads
    for (; base + 32 <= end; base += 32) {
        int s = g_esrc[base + lane];
        float x = g_SS[s] + sd;
        x = (x > 0.f) ? x : 0.01f * x;
        float w = __expf(x);
        den += w;
        #pragma unroll
        for (int t = 0; t < 32; t += 4) {
            int s0 = __shfl_sync(0xffffffffu, s, t + 0);
            int s1 = __shfl_sync(0xffffffffu, s, t + 1);
            int s2 = __shfl_sync(0xffffffffu, s, t + 2);
            int s3 = __shfl_sync(0xffffffffu, s, t + 3);
            float q0 = g_Z[s0 * 32 + lane];
            float q1 = g_Z[s1 * 32 + lane];
            float q2 = g_Z[s2 * 32 + lane];
            float q3 = g_Z[s3 * 32 + lane];
            float w0 = __shfl_sync(0xffffffffu, w, t + 0);
            float w1 = __shfl_sync(0xffffffffu, w, t + 1);
            float w2 = __shfl_sync(0xffffffffu, w, t + 2);
            float w3 = __shfl_sync(0xffffffffu, w, t + 3);
            acc = fmaf(w0, q0, acc);
            acc = fmaf(w1, q1, acc);
            acc = fmaf(w2, q2, acc);
            acc = fmaf(w3, q3, acc);
        }
    }
    // tail
    if (base < end) {
        int idx = base + lane;
        int s = 0;
        float w = 0.f;
        if (idx < end) {
            s = g_esrc[idx];
            float x = g_SS[s] + sd;
            x = (x > 0.f) ? x : 0.01f * x;
            w = __expf(x);
        }
        den += w;
        int cnt = end - base;
        for (int t = 0; t < cnt; t++) {
            int st   = __shfl_sync(0xffffffffu, s, t);
            float wt = __shfl_sync(0xffffffffu, w, t);
            acc = fmaf(wt, g_Z[st * 32 + lane], acc);
        }
    }

    #pragma unroll
    for (int o = 16; o; o >>= 1) den += __shfl_xor_sync(0xffffffffu, den, o);
    float v = acc / fmaxf(den, 1e-9f);
    g_H[n * 32 + lane] = fmaxf(v, 0.f);     // relu, feeds next layer
}

// ===========================================================================
// Gather aggregation, dout==1: one warp per dst node, lanes split edges.
// Fuses normalize + sigmoid, writes final output.
// ===========================================================================
__global__ void gather1_kernel(int N, float* __restrict__ out)
{
    int lane = threadIdx.x & 31;
    int n = blockIdx.x * (blockDim.x >> 5) + (threadIdx.x >> 5);
    if (n >= N) return;

    int beg = g_row[n], end = g_row[n + 1];
    float sd = g_SD[n];
    float acc = 0.f, den = 0.f;
    for (int i = beg + lane; i < end; i += 32) {
        int s = g_esrc[i];
        float x = g_SS[s] + sd;
        x = (x > 0.f) ? x : 0.01f * x;
        float w = __expf(x);
        den += w;
        acc = fmaf(w, g_Z[s], acc);
    }
    #pragma unroll
    for (int o = 16; o; o >>= 1) {
        den += __shfl_xor_sync(0xffffffffu, den, o);
        acc += __shfl_xor_sync(0xffffffffu, acc, o);
    }
    if (lane == 0) {
        float v = acc / fmaxf(den, 1e-9f);
        out[n] = 1.f / (1.f + __expf(-v));
    }
}

// ===========================================================================
extern "C" void kernel_launch(void* const* d_in, const int* in_sizes, int n_in,
                              void* d_out, int out_size)
{
    const float* feat = (const float*)d_in[0];
    const int*   src  = (const int*)d_in[1];
    const int*   dst  = (const int*)d_in[2];
    const float* W1   = (const float*)d_in[3];
    const float* a1   = (const float*)d_in[4];
    const float* W2   = (const float*)d_in[5];
    const float* a2   = (const float*)d_in[6];
    const float* W3   = (const float*)d_in[7];
    const float* a3   = (const float*)d_in[8];

    const int E    = in_sizes[1];
    const int d1   = in_sizes[4] / 2;          // 32
    const int din1 = in_sizes[3] / d1;         // 128
    const int N    = in_sizes[0] / din1;       // 100000
    const int d2   = in_sizes[6] / 2;          // 32
    const int din2 = in_sizes[5] / d2;         // 32
    const int d3   = in_sizes[8] / 2;          // 1
    const int din3 = in_sizes[7] / d3;         // 32
    (void)d2; (void)d3;

    const int NT  = 256;
    const int WPB = NT / 32;
    float* out = (float*)d_out;

    // ---- CSR build (by dst), reused by all 3 layers ----
    const int NB = (N + SCAN_B - 1) / SCAN_B;
    zero_deg_kernel<<<(N + NT - 1) / NT, NT>>>(N);
    hist_kernel<<<(E + NT - 1) / NT, NT>>>(dst, E);
    scan1_kernel<<<NB, SCAN_B>>>(N);
    scan2_kernel<<<1, 256>>>(NB);
    scan3_kernel<<<(N + NT - 1) / NT, NT>>>(N, E);
    scatter_kernel<<<(E + NT - 1) / NT, NT>>>(src, dst, E);

    const int nodeT4Blocks = (N + 4 * WPB - 1) / (4 * WPB);
    const int gatherBlocks = (N + WPB - 1) / WPB;

    // ---- Layer 1 (din=128, dout=32), relu ----
    {
        size_t shm = (size_t)(din1 * 32 + 64 + WPB * 4 * din1) * sizeof(float);
        node_gemm_t4_kernel<<<nodeT4Blocks, NT, shm>>>(feat, 1, W1, a1, N, din1);
        gather32_kernel<<<gatherBlocks, NT>>>(N);
    }
    // ---- Layer 2 (din=32, dout=32), relu ----
    {
        size_t shm = (size_t)(din2 * 32 + 64 + WPB * 4 * din2) * sizeof(float);
        node_gemm_t4_kernel<<<nodeT4Blocks, NT, shm>>>(nullptr, 0, W2, a2, N, din2);
        gather32_kernel<<<gatherBlocks, NT>>>(N);
    }
    // ---- Layer 3 (din=32, dout=1), sigmoid -> d_out ----
    {
        size_t shm = (size_t)(din3 * 1 + 2 + WPB * din3) * sizeof(float);
        node_gemm_kernel<<<gatherBlocks, NT, shm>>>(nullptr, 0, W3, a3, N, din3, 1);
        gather1_kernel<<<gatherBlocks, NT>>>(N, out);
    }
}

// round 9
// speedup vs baseline: 2.6718x; 1.2409x over previous
#include <cuda_runtime.h>

// Problem-fixed maxima (from setup_inputs): N=100000, E=1600000, dims 128->32->32->1.
#define MAXN 100000
#define MAXE 1600000
#define SCAN_B 512
#define MAXNB ((MAXN + SCAN_B - 1) / SCAN_B)   // 196

// ---- scratch (device globals; allocation-free per harness rules) ----
__device__ float g_Z[MAXN * 32];     // layer-1 z
__device__ float g_Z2[MAXN * 32];    // layer-2 z
__device__ float g_Zs[MAXN];         // layer-3 z (scalar)
__device__ float g_SS1[MAXN], g_SD1[MAXN];
__device__ float g_SS2[MAXN], g_SD2[MAXN];
__device__ float g_SS3[MAXN], g_SD3[MAXN];
__device__ int   g_deg[MAXN];
__device__ int   g_row[MAXN + 1];    // CSR row offsets (by dst)
__device__ int   g_cur[MAXN];
__device__ int   g_esrc[MAXE];       // dst-sorted src ids
__device__ int   g_bsum[MAXNB];

// ===========================================================================
// CSR build (dst-sorted)
// ===========================================================================
__global__ void zero_deg_kernel(int N)
{
    int i = blockIdx.x * blockDim.x + threadIdx.x;
    if (i < N) g_deg[i] = 0;
}

__global__ void hist_kernel(const int* __restrict__ dst, int E)
{
    int e = blockIdx.x * blockDim.x + threadIdx.x;
    if (e < E) atomicAdd(&g_deg[dst[e]], 1);
}

// per-block exclusive scan of g_deg into g_row, block totals into g_bsum
__global__ void scan1_kernel(int N)
{
    __shared__ int sh[SCAN_B];
    int tid = threadIdx.x;
    int i = blockIdx.x * SCAN_B + tid;
    int v = (i < N) ? g_deg[i] : 0;
    sh[tid] = v;
    __syncthreads();
    #pragma unroll
    for (int o = 1; o < SCAN_B; o <<= 1) {
        int t = (tid >= o) ? sh[tid - o] : 0;
        __syncthreads();
        sh[tid] += t;
        __syncthreads();
    }
    if (i < N) g_row[i] = sh[tid] - v;          // exclusive
    if (tid == SCAN_B - 1) g_bsum[blockIdx.x] = sh[tid];
}

// scan3: every block locally scans the (<=196) block sums in shared, then
// applies the offset, initializes cursors, closes the row array.
// (Replaces the old single-block scan2 + scan3 pair.)
__global__ void scan3_kernel(int N, int E, int NB)
{
    __shared__ int sb[256];
    int tid = threadIdx.x;
    int v = (tid < NB) ? g_bsum[tid] : 0;
    sb[tid] = v;
    __syncthreads();
    #pragma unroll
    for (int o = 1; o < 256; o <<= 1) {
        int t = (tid >= o) ? sb[tid - o] : 0;
        __syncthreads();
        sb[tid] += t;
        __syncthreads();
    }
    int inc = sb[tid];
    __syncthreads();
    sb[tid] = inc - v;                          // exclusive block offsets
    __syncthreads();

    int i = blockIdx.x * blockDim.x + tid;
    if (i < N) {
        int r = g_row[i] + sb[i / SCAN_B];
        g_row[i] = r;
        g_cur[i] = r;
    }
    if (i == 0) g_row[N] = E;
}

__global__ void scatter_kernel(const int* __restrict__ src,
                               const int* __restrict__ dst, int E)
{
    int e = blockIdx.x * blockDim.x + threadIdx.x;
    if (e < E) {
        int p = atomicAdd(&g_cur[dst[e]], 1);
        g_esrc[p] = src[e];
    }
}

// ===========================================================================
// Layer-1 node pass: z = feat@W1, s_src/s_dst. dout=32, 4 nodes per warp.
// ===========================================================================
__global__ void node_gemm_t4_kernel(const float* __restrict__ hext,
                                    const float* __restrict__ W,
                                    const float* __restrict__ a,
                                    int N, int din)
{
    extern __shared__ float sh[];
    float* Ws = sh;                // din*32
    float* as = Ws + din * 32;     // 64
    float* hs = as + 64;           // WPB * 4 * din

    int tid = threadIdx.x;
    for (int i = tid; i < din * 32; i += blockDim.x) Ws[i] = W[i];
    for (int i = tid; i < 64; i += blockDim.x) as[i] = a[i];
    __syncthreads();

    int lane = tid & 31;
    int wrp  = tid >> 5;
    int WPB  = blockDim.x >> 5;
    float* hw = hs + wrp * 4 * din;

    int n0 = (blockIdx.x * WPB + wrp) * 4;
    if (n0 >= N) return;
    int cnt = (N - n0 < 4) ? (N - n0) : 4;

    for (int t = 0; t < cnt; t++) {
        const float* hr = hext + (long long)(n0 + t) * din;
        for (int k = lane; k < din; k += 32) hw[t * din + k] = hr[k];
    }
    for (int t = cnt; t < 4; t++)
        for (int k = lane; k < din; k += 32) hw[t * din + k] = 0.f;
    __syncwarp();

    float z0 = 0.f, z1 = 0.f, z2 = 0.f, z3 = 0.f;
    #pragma unroll 8
    for (int k = 0; k < din; k++) {
        float wv = Ws[k * 32 + lane];
        z0 = fmaf(hw[k],           wv, z0);
        z1 = fmaf(hw[din + k],     wv, z1);
        z2 = fmaf(hw[2 * din + k], wv, z2);
        z3 = fmaf(hw[3 * din + k], wv, z3);
    }
    float zz[4] = {z0, z1, z2, z3};
    float aS = as[lane], aD = as[32 + lane];
    for (int t = 0; t < cnt; t++) {
        int n = n0 + t;
        g_Z[n * 32 + lane] = zz[t];
        float ps = zz[t] * aS, pd = zz[t] * aD;
        #pragma unroll
        for (int o = 16; o; o >>= 1) {
            ps += __shfl_down_sync(0xffffffffu, ps, o);
            pd += __shfl_down_sync(0xffffffffu, pd, o);
        }
        if (lane == 0) { g_SS1[n] = ps; g_SD1[n] = pd; }
    }
}

// ===========================================================================
// Gather core: 2 dst nodes per warp, 16 lanes (float2 features) per node.
// Warp-uniform loops (zero-padded weights) keep full-mask shuffles legal.
// Returns h = relu-less normalized aggregate in acc; caller applies epilogue.
// ===========================================================================
#define GATHER_CORE(SScur, SDcur, ZSRC)                                        \
    int lane   = threadIdx.x & 31;                                             \
    int lane16 = lane & 15;                                                    \
    int half   = lane >> 4;                                                    \
    int wrp    = threadIdx.x >> 5;                                             \
    int pair   = blockIdx.x * (blockDim.x >> 5) + wrp;                         \
    int n      = pair * 2 + half;                                              \
    bool valid = (n < N);                                                      \
    int beg = 0, cnt = 0; float sd = 0.f;                                      \
    if (valid) { beg = g_row[n]; cnt = g_row[n + 1] - beg; sd = SDcur[n]; }    \
    int cntmax = max(cnt, __shfl_xor_sync(0xffffffffu, cnt, 16));              \
    const float2* Zv = (const float2*)ZSRC;                                    \
    float2 acc = make_float2(0.f, 0.f);                                        \
    float den = 0.f;                                                           \
    for (int base = 0; base < cntmax; base += 16) {                            \
        int m = cnt - base;                                                    \
        int s = 0; float w = 0.f;                                              \
        if (lane16 < m) {                                                      \
            s = g_esrc[beg + base + lane16];                                   \
            float x = SScur[s] + sd;                                           \
            x = (x > 0.f) ? x : 0.01f * x;                                     \
            w = __expf(x);                                                     \
        }                                                                      \
        den += w;                                                              \
        int mmax = min(16, cntmax - base);                                     \
        int t = 0;                                                             \
        for (; t + 4 <= mmax; t += 4) {                                        \
            int b = half * 16 + t;                                             \
            int s0 = __shfl_sync(0xffffffffu, s, b + 0);                       \
            int s1 = __shfl_sync(0xffffffffu, s, b + 1);                       \
            int s2 = __shfl_sync(0xffffffffu, s, b + 2);                       \
            int s3 = __shfl_sync(0xffffffffu, s, b + 3);                       \
            float w0 = __shfl_sync(0xffffffffu, w, b + 0);                     \
            float w1 = __shfl_sync(0xffffffffu, w, b + 1);                     \
            float w2 = __shfl_sync(0xffffffffu, w, b + 2);                     \
            float w3 = __shfl_sync(0xffffffffu, w, b + 3);                     \
            float2 q0 = Zv[s0 * 16 + lane16];                                  \
            float2 q1 = Zv[s1 * 16 + lane16];                                  \
            float2 q2 = Zv[s2 * 16 + lane16];                                  \
            float2 q3 = Zv[s3 * 16 + lane16];                                  \
            acc.x = fmaf(w0, q0.x, acc.x); acc.y = fmaf(w0, q0.y, acc.y);      \
            acc.x = fmaf(w1, q1.x, acc.x); acc.y = fmaf(w1, q1.y, acc.y);      \
            acc.x = fmaf(w2, q2.x, acc.x); acc.y = fmaf(w2, q2.y, acc.y);      \
            acc.x = fmaf(w3, q3.x, acc.x); acc.y = fmaf(w3, q3.y, acc.y);      \
        }                                                                      \
        for (; t < mmax; t++) {                                                \
            int b = half * 16 + t;                                             \
            int st   = __shfl_sync(0xffffffffu, s, b);                         \
            float wt = __shfl_sync(0xffffffffu, w, b);                         \
            float2 q = Zv[st * 16 + lane16];                                   \
            acc.x = fmaf(wt, q.x, acc.x); acc.y = fmaf(wt, q.y, acc.y);        \
        }                                                                      \
    }                                                                          \
    _Pragma("unroll")                                                          \
    for (int o = 8; o; o >>= 1) den += __shfl_xor_sync(0xffffffffu, den, o);   \
    float inv = 1.f / fmaxf(den, 1e-9f);                                       \
    float2 h;                                                                  \
    h.x = fmaxf(acc.x * inv, 0.f);                                             \
    h.y = fmaxf(acc.y * inv, 0.f);

// ---------------------------------------------------------------------------
// Gather layer 1 + fused layer-2 node GEMM (z2 = h@W2, s_src2, s_dst2).
// ---------------------------------------------------------------------------
__global__ void gather_fuse_L1L2_kernel(int N, const float* __restrict__ W2,
                                        const float* __restrict__ a2)
{
    __shared__ float W2s[32 * 32];
    __shared__ float a2s[64];
    int tid0 = threadIdx.x;
    for (int i = tid0; i < 32 * 32; i += blockDim.x) W2s[i] = W2[i];
    if (tid0 < 64) a2s[tid0] = a2[tid0];
    __syncthreads();

    GATHER_CORE(g_SS1, g_SD1, g_Z)

    // z2 = h @ W2 ; this lane owns output features (2*lane16, 2*lane16+1)
    const float2* W2v = (const float2*)W2s;
    float2 z2 = make_float2(0.f, 0.f);
    #pragma unroll
    for (int jj = 0; jj < 16; jj++) {
        int b = half * 16 + jj;
        float hx = __shfl_sync(0xffffffffu, h.x, b);   // feature 2*jj
        float hy = __shfl_sync(0xffffffffu, h.y, b);   // feature 2*jj+1
        float2 r0 = W2v[(2 * jj)     * 16 + lane16];
        float2 r1 = W2v[(2 * jj + 1) * 16 + lane16];
        z2.x = fmaf(hx, r0.x, fmaf(hy, r1.x, z2.x));
        z2.y = fmaf(hx, r0.y, fmaf(hy, r1.y, z2.y));
    }
    float ps = z2.x * a2s[2 * lane16]      + z2.y * a2s[2 * lane16 + 1];
    float pd = z2.x * a2s[32 + 2 * lane16] + z2.y * a2s[32 + 2 * lane16 + 1];
    #pragma unroll
    for (int o = 8; o; o >>= 1) {
        ps += __shfl_xor_sync(0xffffffffu, ps, o);
        pd += __shfl_xor_sync(0xffffffffu, pd, o);
    }
    if (valid) {
        ((float2*)g_Z2)[n * 16 + lane16] = z2;
        if (lane16 == 0) { g_SS2[n] = ps; g_SD2[n] = pd; }
    }
}

// ---------------------------------------------------------------------------
// Gather layer 2 + fused layer-3 node GEMM (scalar z3 = h.W3, s3 scalars).
// ---------------------------------------------------------------------------
__global__ void gather_fuse_L2L3_kernel(int N, const float* __restrict__ W3,
                                        const float* __restrict__ a3)
{
    __shared__ float W3s[32];
    __shared__ float a3s[2];
    int tid0 = threadIdx.x;
    if (tid0 < 32) W3s[tid0] = W3[tid0];
    if (tid0 < 2)  a3s[tid0] = a3[tid0];
    __syncthreads();

    GATHER_CORE(g_SS2, g_SD2, g_Z2)

    float z3 = h.x * W3s[2 * lane16] + h.y * W3s[2 * lane16 + 1];
    #pragma unroll
    for (int o = 8; o; o >>= 1) z3 += __shfl_xor_sync(0xffffffffu, z3, o);
    if (valid && lane16 == 0) {
        g_Zs[n]  = z3;
        g_SS3[n] = z3 * a3s[0];
        g_SD3[n] = z3 * a3s[1];
    }
}

// ---------------------------------------------------------------------------
// Final gather (dout=1): 2 nodes per warp, normalize + sigmoid -> output.
// ---------------------------------------------------------------------------
__global__ void gather1_kernel(int N, float* __restrict__ out)
{
    int lane   = threadIdx.x & 31;
    int lane16 = lane & 15;
    int half   = lane >> 4;
    int wrp    = threadIdx.x >> 5;
    int pair   = blockIdx.x * (blockDim.x >> 5) + wrp;
    int n      = pair * 2 + half;
    bool valid = (n < N);
    int beg = 0, end = 0; float sd = 0.f;
    if (valid) { beg = g_row[n]; end = g_row[n + 1]; sd = g_SD3[n]; }

    float acc = 0.f, den = 0.f;
    for (int i = beg + lane16; i < end; i += 16) {
        int s = g_esrc[i];
        float x = g_SS3[s] + sd;
        x = (x > 0.f) ? x : 0.01f * x;
        float w = __expf(x);
        den += w;
        acc = fmaf(w, g_Zs[s], acc);
    }
    #pragma unroll
    for (int o = 8; o; o >>= 1) {
        den += __shfl_xor_sync(0xffffffffu, den, o);
        acc += __shfl_xor_sync(0xffffffffu, acc, o);
    }
    if (valid && lane16 == 0) {
        float v = acc / fmaxf(den, 1e-9f);
        out[n] = 1.f / (1.f + __expf(-v));
    }
}

// ===========================================================================
extern "C" void kernel_launch(void* const* d_in, const int* in_sizes, int n_in,
                              void* d_out, int out_size)
{
    const float* feat = (const float*)d_in[0];
    const int*   src  = (const int*)d_in[1];
    const int*   dst  = (const int*)d_in[2];
    const float* W1   = (const float*)d_in[3];
    const float* a1   = (const float*)d_in[4];
    const float* W2   = (const float*)d_in[5];
    const float* a2   = (const float*)d_in[6];
    const float* W3   = (const float*)d_in[7];
    const float* a3   = (const float*)d_in[8];

    const int E    = in_sizes[1];
    const int d1   = in_sizes[4] / 2;          // 32
    const int din1 = in_sizes[3] / d1;         // 128
    const int N    = in_sizes[0] / din1;       // 100000

    const int NT  = 256;
    const int WPB = NT / 32;
    float* out = (float*)d_out;

    // ---- CSR build (by dst), reused by all 3 layers ----
    const int NB = (N + SCAN_B - 1) / SCAN_B;
    zero_deg_kernel<<<(N + NT - 1) / NT, NT>>>(N);
    hist_kernel<<<(E + NT - 1) / NT, NT>>>(dst, E);
    scan1_kernel<<<NB, SCAN_B>>>(N);
    scan3_kernel<<<(N + NT - 1) / NT, NT>>>(N, E, NB);
    scatter_kernel<<<(E + NT - 1) / NT, NT>>>(src, dst, E);

    // ---- Layer 1 node GEMM ----
    {
        const int nodeT4Blocks = (N + 4 * WPB - 1) / (4 * WPB);
        size_t shm = (size_t)(din1 * 32 + 64 + WPB * 4 * din1) * sizeof(float);
        node_gemm_t4_kernel<<<nodeT4Blocks, NT, shm>>>(feat, W1, a1, N, din1);
    }

    // ---- Gather chains (2 nodes/warp) ----
    const int pairs = (N + 1) / 2;
    const int gBlocks = (pairs + WPB - 1) / WPB;
    gather_fuse_L1L2_kernel<<<gBlocks, NT>>>(N, W2, a2);
    gather_fuse_L2L3_kernel<<<gBlocks, NT>>>(N, W3, a3);
    gather1_kernel<<<gBlocks, NT>>>(N, out);
}

// round 10
// speedup vs baseline: 3.0245x; 1.1320x over previous
#include <cuda_runtime.h>

// Problem-fixed maxima (from setup_inputs): N=100000, E=1600000, dims 128->32->32->1.
#define MAXN 100000
#define MAXE 1600000
#define SCAN_B 512
#define MAXNB ((MAXN + SCAN_B - 1) / SCAN_B)   // 196

// ---- scratch (device globals; allocation-free per harness rules) ----
__device__ float g_Z[MAXN * 32];     // layer-1 z
__device__ float g_Z2[MAXN * 32];    // layer-2 z
__device__ float g_Zs[MAXN];         // layer-3 z (scalar)
__device__ float g_SS1[MAXN], g_SD1[MAXN];
__device__ float g_SS2[MAXN], g_SD2[MAXN];
__device__ float g_SS3[MAXN], g_SD3[MAXN];
__device__ int   g_deg[MAXN];
__device__ int   g_row[MAXN + 1];    // CSR row offsets (by dst)
__device__ int   g_cur[MAXN];
__device__ int   g_esrc[MAXE];       // dst-sorted src ids
__device__ int   g_bsum[MAXNB];
__device__ int   g_scan_ctr;         // decoupled-scan completion counter

// ===========================================================================
// init: zero degree histogram + reset scan counter (runs first every launch)
// ===========================================================================
__global__ void init_kernel(int N)
{
    int i = blockIdx.x * blockDim.x + threadIdx.x;
    if (i < N) g_deg[i] = 0;
    if (i == 0) g_scan_ctr = 0;
}

// ===========================================================================
// Fused: dst histogram (blocks [0, histBlocks)) + layer-1 node GEMM
// (blocks [histBlocks, ...)). Independent work co-scheduled on the chip.
// GEMM: z = feat@W1, s_src1/s_dst1. dout=32, 4 nodes per warp.
// ===========================================================================
__global__ void __launch_bounds__(256)
hist_gemm_kernel(const int* __restrict__ dst, int E, int histBlocks,
                 const float* __restrict__ feat,
                 const float* __restrict__ W,
                 const float* __restrict__ a,
                 int N, int din)
{
    if (blockIdx.x < histBlocks) {
        int e = blockIdx.x * blockDim.x + threadIdx.x;
        if (e < E) atomicAdd(&g_deg[dst[e]], 1);
        return;
    }
    int bid = blockIdx.x - histBlocks;

    extern __shared__ float sh[];
    float* Ws = sh;                // din*32
    float* as = Ws + din * 32;     // 64
    float* hs = as + 64;           // WPB * 4 * din

    int tid = threadIdx.x;
    for (int i = tid; i < din * 32; i += blockDim.x) Ws[i] = W[i];
    for (int i = tid; i < 64; i += blockDim.x) as[i] = a[i];
    __syncthreads();

    int lane = tid & 31;
    int wrp  = tid >> 5;
    int WPB  = blockDim.x >> 5;
    float* hw = hs + wrp * 4 * din;

    int n0 = (bid * WPB + wrp) * 4;
    if (n0 >= N) return;
    int cnt = (N - n0 < 4) ? (N - n0) : 4;

    for (int t = 0; t < cnt; t++) {
        const float* hr = feat + (long long)(n0 + t) * din;
        for (int k = lane; k < din; k += 32) hw[t * din + k] = hr[k];
    }
    for (int t = cnt; t < 4; t++)
        for (int k = lane; k < din; k += 32) hw[t * din + k] = 0.f;
    __syncwarp();

    float z0 = 0.f, z1 = 0.f, z2 = 0.f, z3 = 0.f;
    #pragma unroll 8
    for (int k = 0; k < din; k++) {
        float wv = Ws[k * 32 + lane];
        z0 = fmaf(hw[k],           wv, z0);
        z1 = fmaf(hw[din + k],     wv, z1);
        z2 = fmaf(hw[2 * din + k], wv, z2);
        z3 = fmaf(hw[3 * din + k], wv, z3);
    }
    float zz[4] = {z0, z1, z2, z3};
    float aS = as[lane], aD = as[32 + lane];
    for (int t = 0; t < cnt; t++) {
        int n = n0 + t;
        g_Z[n * 32 + lane] = zz[t];
        float ps = zz[t] * aS, pd = zz[t] * aD;
        #pragma unroll
        for (int o = 16; o; o >>= 1) {
            ps += __shfl_down_sync(0xffffffffu, ps, o);
            pd += __shfl_down_sync(0xffffffffu, pd, o);
        }
        if (lane == 0) { g_SS1[n] = ps; g_SD1[n] = pd; }
    }
}

// ===========================================================================
// scan1: per-block exclusive scan of g_deg into g_row, block totals to g_bsum.
// Decoupled finale: the LAST finishing block exclusive-scans g_bsum in place.
// ===========================================================================
__global__ void scan1_kernel(int N, int NB)
{
    __shared__ int sh[SCAN_B];
    __shared__ int flagS;
    int tid = threadIdx.x;
    int i = blockIdx.x * SCAN_B + tid;
    int v = (i < N) ? g_deg[i] : 0;
    sh[tid] = v;
    __syncthreads();
    #pragma unroll
    for (int o = 1; o < SCAN_B; o <<= 1) {
        int t = (tid >= o) ? sh[tid - o] : 0;
        __syncthreads();
        sh[tid] += t;
        __syncthreads();
    }
    if (i < N) g_row[i] = sh[tid] - v;          // exclusive within block
    if (tid == SCAN_B - 1) g_bsum[blockIdx.x] = sh[tid];

    // decoupled last-block scan of the block sums
    __threadfence();
    if (tid == 0) flagS = (atomicAdd(&g_scan_ctr, 1) == gridDim.x - 1);
    __syncthreads();
    if (flagS) {
        int bv = (tid < NB) ? g_bsum[tid] : 0;
        sh[tid] = bv;
        __syncthreads();
        #pragma unroll
        for (int o = 1; o < SCAN_B; o <<= 1) {
            int t = (tid >= o) ? sh[tid - o] : 0;
            __syncthreads();
            sh[tid] += t;
            __syncthreads();
        }
        if (tid < NB) g_bsum[tid] = sh[tid] - bv;   // exclusive
    }
}

// apply block offsets, init cursors, close the row array
__global__ void scan_apply_kernel(int N, int E)
{
    int i = blockIdx.x * blockDim.x + threadIdx.x;
    if (i < N) {
        int r = g_row[i] + g_bsum[i / SCAN_B];
        g_row[i] = r;
        g_cur[i] = r;
    }
    if (i == 0) g_row[N] = E;
}

__global__ void scatter_kernel(const int* __restrict__ src,
                               const int* __restrict__ dst, int E)
{
    int e = blockIdx.x * blockDim.x + threadIdx.x;
    if (e < E) {
        int p = atomicAdd(&g_cur[dst[e]], 1);
        g_esrc[p] = src[e];
    }
}

// ===========================================================================
// Gather core: 4 dst nodes per warp, 8 lanes (float4 features) per node.
// Per inner step: 2 SHFL + 1 LDG.128 + 4 FMA advance 4 edges (one per quarter).
// Warp-uniform trip count (cntmax over the 4 quarters), padded lanes get w=0.
// ===========================================================================
#define GATHER4_CORE(SScur, SDcur, ZSRC)                                       \
    int lane = threadIdx.x & 31;                                               \
    int l8   = lane & 7;                                                       \
    int qb   = lane & 24;          /* quarter*8 */                             \
    int wrp  = threadIdx.x >> 5;                                               \
    int warpid = blockIdx.x * (blockDim.x >> 5) + wrp;                         \
    int n = warpid * 4 + (lane >> 3);                                          \
    bool valid = (n < N);                                                      \
    int beg = 0, cnt = 0; float sd = 0.f;                                      \
    if (valid) { beg = g_row[n]; cnt = g_row[n + 1] - beg; sd = SDcur[n]; }    \
    int cntmax = cnt;                                                          \
    cntmax = max(cntmax, __shfl_xor_sync(0xffffffffu, cntmax, 8));             \
    cntmax = max(cntmax, __shfl_xor_sync(0xffffffffu, cntmax, 16));            \
    const float4* Zv = (const float4*)ZSRC;                                    \
    float4 acc = make_float4(0.f, 0.f, 0.f, 0.f);                              \
    float den = 0.f;                                                           \
    for (int base = 0; base < cntmax; base += 8) {                             \
        int s = 0; float w = 0.f;                                              \
        if (l8 < cnt - base) {                                                 \
            s = g_esrc[beg + base + l8];                                       \
            float x = SScur[s] + sd;                                           \
            x = (x > 0.f) ? x : 0.01f * x;                                     \
            w = __expf(x);                                                     \
        }                                                                      \
        den += w;                                                              \
        _Pragma("unroll")                                                      \
        for (int t = 0; t < 8; t++) {                                          \
            int b = qb | t;                                                    \
            int st   = __shfl_sync(0xffffffffu, s, b);                         \
            float wt = __shfl_sync(0xffffffffu, w, b);                         \
            float4 qv = Zv[st * 8 + l8];                                       \
            acc.x = fmaf(wt, qv.x, acc.x);                                     \
            acc.y = fmaf(wt, qv.y, acc.y);                                     \
            acc.z = fmaf(wt, qv.z, acc.z);                                     \
            acc.w = fmaf(wt, qv.w, acc.w);                                     \
        }                                                                      \
    }                                                                          \
    _Pragma("unroll")                                                          \
    for (int o = 4; o; o >>= 1) den += __shfl_xor_sync(0xffffffffu, den, o);   \
    float inv = 1.f / fmaxf(den, 1e-9f);                                       \
    float4 h;                                                                  \
    h.x = fmaxf(acc.x * inv, 0.f);                                             \
    h.y = fmaxf(acc.y * inv, 0.f);                                             \
    h.z = fmaxf(acc.z * inv, 0.f);                                             \
    h.w = fmaxf(acc.w * inv, 0.f);
// h holds relu'd features (4*l8 .. 4*l8+3) of node n.

// ---------------------------------------------------------------------------
// Gather layer 1 + fused layer-2 node GEMM (z2 = h@W2, s_src2, s_dst2).
// ---------------------------------------------------------------------------
__global__ void __launch_bounds__(256)
gather_fuse_L1L2_kernel(int N, const float* __restrict__ W2,
                        const float* __restrict__ a2)
{
    __shared__ float W2s[32 * 32];
    __shared__ float a2s[64];
    int tid0 = threadIdx.x;
    for (int i = tid0; i < 32 * 32; i += blockDim.x) W2s[i] = W2[i];
    if (tid0 < 64) a2s[tid0] = a2[tid0];
    __syncthreads();

    GATHER4_CORE(g_SS1, g_SD1, g_Z)

    // z2 = h @ W2 ; this lane owns output features 4*l8 .. 4*l8+3
    const float4* W2v = (const float4*)W2s;
    float4 z2 = make_float4(0.f, 0.f, 0.f, 0.f);
    #pragma unroll
    for (int k8 = 0; k8 < 8; k8++) {
        int b = qb | k8;
        float hx = __shfl_sync(0xffffffffu, h.x, b);   // input feature 4*k8
        float hy = __shfl_sync(0xffffffffu, h.y, b);
        float hz = __shfl_sync(0xffffffffu, h.z, b);
        float hv = __shfl_sync(0xffffffffu, h.w, b);
        float4 r0 = W2v[(4 * k8 + 0) * 8 + l8];
        float4 r1 = W2v[(4 * k8 + 1) * 8 + l8];
        float4 r2 = W2v[(4 * k8 + 2) * 8 + l8];
        float4 r3 = W2v[(4 * k8 + 3) * 8 + l8];
        z2.x = fmaf(hx, r0.x, fmaf(hy, r1.x, fmaf(hz, r2.x, fmaf(hv, r3.x, z2.x))));
        z2.y = fmaf(hx, r0.y, fmaf(hy, r1.y, fmaf(hz, r2.y, fmaf(hv, r3.y, z2.y))));
        z2.z = fmaf(hx, r0.z, fmaf(hy, r1.z, fmaf(hz, r2.z, fmaf(hv, r3.z, z2.z))));
        z2.w = fmaf(hx, r0.w, fmaf(hy, r1.w, fmaf(hz, r2.w, fmaf(hv, r3.w, z2.w))));
    }
    float ps = z2.x * a2s[4 * l8]     + z2.y * a2s[4 * l8 + 1]
             + z2.z * a2s[4 * l8 + 2] + z2.w * a2s[4 * l8 + 3];
    float pd = z2.x * a2s[32 + 4 * l8]     + z2.y * a2s[32 + 4 * l8 + 1]
             + z2.z * a2s[32 + 4 * l8 + 2] + z2.w * a2s[32 + 4 * l8 + 3];
    #pragma unroll
    for (int o = 4; o; o >>= 1) {
        ps += __shfl_xor_sync(0xffffffffu, ps, o);
        pd += __shfl_xor_sync(0xffffffffu, pd, o);
    }
    if (valid) {
        ((float4*)g_Z2)[n * 8 + l8] = z2;
        if (l8 == 0) { g_SS2[n] = ps; g_SD2[n] = pd; }
    }
}

// ---------------------------------------------------------------------------
// Gather layer 2 + fused layer-3 node GEMM (scalar z3 = h.W3, s3 scalars).
// ---------------------------------------------------------------------------
__global__ void __launch_bounds__(256)
gather_fuse_L2L3_kernel(int N, const float* __restrict__ W3,
                        const float* __restrict__ a3)
{
    __shared__ float W3s[32];
    __shared__ float a3s[2];
    int tid0 = threadIdx.x;
    if (tid0 < 32) W3s[tid0] = W3[tid0];
    if (tid0 < 2)  a3s[tid0] = a3[tid0];
    __syncthreads();

    GATHER4_CORE(g_SS2, g_SD2, g_Z2)

    float z3 = h.x * W3s[4 * l8]     + h.y * W3s[4 * l8 + 1]
             + h.z * W3s[4 * l8 + 2] + h.w * W3s[4 * l8 + 3];
    #pragma unroll
    for (int o = 4; o; o >>= 1) z3 += __shfl_xor_sync(0xffffffffu, z3, o);
    if (valid && l8 == 0) {
        g_Zs[n]  = z3;
        g_SS3[n] = z3 * a3s[0];
        g_SD3[n] = z3 * a3s[1];
    }
}

// ---------------------------------------------------------------------------
// Final gather (dout=1): 4 nodes per warp, normalize + sigmoid -> output.
// ---------------------------------------------------------------------------
__global__ void __launch_bounds__(256)
gather1_kernel(int N, float* __restrict__ out)
{
    int lane = threadIdx.x & 31;
    int l8   = lane & 7;
    int wrp  = threadIdx.x >> 5;
    int warpid = blockIdx.x * (blockDim.x >> 5) + wrp;
    int n = warpid * 4 + (lane >> 3);
    bool valid = (n < N);
    int beg = 0, end = 0; float sd = 0.f;
    if (valid) { beg = g_row[n]; end = g_row[n + 1]; sd = g_SD3[n]; }

    float acc = 0.f, den = 0.f;
    for (int i = beg + l8; i < end; i += 8) {
        int s = g_esrc[i];
        float x = g_SS3[s] + sd;
        x = (x > 0.f) ? x : 0.01f * x;
        float w = __expf(x);
        den += w;
        acc = fmaf(w, g_Zs[s], acc);
    }
    #pragma unroll
    for (int o = 4; o; o >>= 1) {
        den += __shfl_xor_sync(0xffffffffu, den, o);
        acc += __shfl_xor_sync(0xffffffffu, acc, o);
    }
    if (valid && l8 == 0) {
        float v = acc / fmaxf(den, 1e-9f);
        out[n] = 1.f / (1.f + __expf(-v));
    }
}

// ===========================================================================
extern "C" void kernel_launch(void* const* d_in, const int* in_sizes, int n_in,
                              void* d_out, int out_size)
{
    const float* feat = (const float*)d_in[0];
    const int*   src  = (const int*)d_in[1];
    const int*   dst  = (const int*)d_in[2];
    const float* W1   = (const float*)d_in[3];
    const float* a1   = (const float*)d_in[4];
    const float* W2   = (const float*)d_in[5];
    const float* a2   = (const float*)d_in[6];
    const float* W3   = (const float*)d_in[7];
    const float* a3   = (const float*)d_in[8];

    const int E    = in_sizes[1];
    const int d1   = in_sizes[4] / 2;          // 32
    const int din1 = in_sizes[3] / d1;         // 128
    const int N    = in_sizes[0] / din1;       // 100000

    const int NT  = 256;
    const int WPB = NT / 32;                   // 8 warps/block
    float* out = (float*)d_out;

    // ---- init ----
    init_kernel<<<(N + NT - 1) / NT, NT>>>(N);

    // ---- fused dst-histogram + layer-1 node GEMM ----
    const int histBlocks = (E + NT - 1) / NT;
    const int gemmBlocks = (N + 4 * WPB * 1 - 1) / (4 * WPB) / 1;  // 4 nodes/warp
    {
        size_t shm = (size_t)(din1 * 32 + 64 + WPB * 4 * din1) * sizeof(float);
        hist_gemm_kernel<<<histBlocks + gemmBlocks, NT, shm>>>(
            dst, E, histBlocks, feat, W1, a1, N, din1);
    }

    // ---- CSR scan + scatter ----
    const int NB = (N + SCAN_B - 1) / SCAN_B;
    scan1_kernel<<<NB, SCAN_B>>>(N, NB);
    scan_apply_kernel<<<(N + NT - 1) / NT, NT>>>(N, E);
    scatter_kernel<<<histBlocks, NT>>>(src, dst, E);

    // ---- Gather chains (4 nodes/warp, 8 lanes/node) ----
    const int quads = (N + 3) / 4;
    const int gBlocks = (quads + WPB - 1) / WPB;
    gather_fuse_L1L2_kernel<<<gBlocks, NT>>>(N, W2, a2);
    gather_fuse_L2L3_kernel<<<gBlocks, NT>>>(N, W3, a3);
    gather1_kernel<<<gBlocks, NT>>>(N, out);
}

// round 11
// speedup vs baseline: 3.2513x; 1.0750x over previous
#include <cuda_runtime.h>
#include <cuda_fp16.h>

// Problem-fixed maxima (from setup_inputs): N=100000, E=1600000, dims 128->32->32->1.
#define MAXN 100000
#define MAXE 1600000
#define SCAN_B 512
#define MAXNB ((MAXN + SCAN_B - 1) / SCAN_B)   // 196

// ---- scratch (device globals; allocation-free per harness rules) ----
// Zero-initialized at module load; every launch restores g_deg==0 and
// g_scan_ctr==0 (scatter decrements deg back to 0; scan1 last block resets ctr),
// so graph replays see identical initial state.
__device__ __half g_Zh[MAXN * 32];   // layer-1 z (fp16 for gather bandwidth)
__device__ __half g_Z2h[MAXN * 32];  // layer-2 z (fp16)
__device__ float g_Zs[MAXN];         // layer-3 z (scalar, fp32)
__device__ float g_SS1[MAXN], g_SD1[MAXN];
__device__ float g_SS2[MAXN], g_SD2[MAXN];
__device__ float g_SS3[MAXN], g_SD3[MAXN];
__device__ int   g_deg[MAXN];        // degree counters (return to 0 each launch)
__device__ int   g_row[MAXN + 1];    // block-local exclusive scan of deg
__device__ int   g_bsum[MAXNB];      // exclusive-scanned block sums
__device__ int   g_esrc[MAXE];       // dst-sorted src ids
__device__ int   g_scan_ctr;         // decoupled-scan counter (self-resetting)

// row_final(i) = g_row[i] + g_bsum[i >> 9]  (valid for 0..N; g_row[N] patched)

// ===========================================================================
// Fused: dst histogram (blocks [0, histBlocks)) + layer-1 node GEMM
// (blocks [histBlocks, ...)). Independent work co-scheduled on the chip.
// GEMM: z = feat@W1 (stored fp16), s_src1/s_dst1. dout=32, 4 nodes per warp.
// ===========================================================================
__global__ void __launch_bounds__(256)
hist_gemm_kernel(const int* __restrict__ dst, int E, int histBlocks,
                 const float* __restrict__ feat,
                 const float* __restrict__ W,
                 const float* __restrict__ a,
                 int N, int din)
{
    if (blockIdx.x < histBlocks) {
        int e = blockIdx.x * blockDim.x + threadIdx.x;
        if (e < E) atomicAdd(&g_deg[dst[e]], 1);
        return;
    }
    int bid = blockIdx.x - histBlocks;

    extern __shared__ float sh[];
    float* Ws = sh;                // din*32
    float* as = Ws + din * 32;     // 64
    float* hs = as + 64;           // WPB * 4 * din

    int tid = threadIdx.x;
    for (int i = tid; i < din * 32; i += blockDim.x) Ws[i] = W[i];
    for (int i = tid; i < 64; i += blockDim.x) as[i] = a[i];
    __syncthreads();

    int lane = tid & 31;
    int wrp  = tid >> 5;
    int WPB  = blockDim.x >> 5;
    float* hw = hs + wrp * 4 * din;

    int n0 = (bid * WPB + wrp) * 4;
    if (n0 >= N) return;
    int cnt = (N - n0 < 4) ? (N - n0) : 4;

    for (int t = 0; t < cnt; t++) {
        const float* hr = feat + (long long)(n0 + t) * din;
        for (int k = lane; k < din; k += 32) hw[t * din + k] = hr[k];
    }
    for (int t = cnt; t < 4; t++)
        for (int k = lane; k < din; k += 32) hw[t * din + k] = 0.f;
    __syncwarp();

    float z0 = 0.f, z1 = 0.f, z2 = 0.f, z3 = 0.f;
    #pragma unroll 8
    for (int k = 0; k < din; k++) {
        float wv = Ws[k * 32 + lane];
        z0 = fmaf(hw[k],           wv, z0);
        z1 = fmaf(hw[din + k],     wv, z1);
        z2 = fmaf(hw[2 * din + k], wv, z2);
        z3 = fmaf(hw[3 * din + k], wv, z3);
    }
    float zz[4] = {z0, z1, z2, z3};
    float aS = as[lane], aD = as[32 + lane];
    for (int t = 0; t < cnt; t++) {
        int n = n0 + t;
        g_Zh[n * 32 + lane] = __float2half(zz[t]);
        float ps = zz[t] * aS, pd = zz[t] * aD;
        #pragma unroll
        for (int o = 16; o; o >>= 1) {
            ps += __shfl_down_sync(0xffffffffu, ps, o);
            pd += __shfl_down_sync(0xffffffffu, pd, o);
        }
        if (lane == 0) { g_SS1[n] = ps; g_SD1[n] = pd; }
    }
}

// ===========================================================================
// scan1: per-block exclusive scan of g_deg into g_row, block totals to g_bsum.
// Decoupled finale: LAST finishing block exclusive-scans g_bsum in place,
// patches g_row[N] so row_final(N)==E, and resets g_scan_ctr for next replay.
// ===========================================================================
__global__ void scan1_kernel(int N, int E, int NB)
{
    __shared__ int sh[SCAN_B];
    __shared__ int flagS;
    int tid = threadIdx.x;
    int i = blockIdx.x * SCAN_B + tid;
    int v = (i < N) ? g_deg[i] : 0;
    sh[tid] = v;
    __syncthreads();
    #pragma unroll
    for (int o = 1; o < SCAN_B; o <<= 1) {
        int t = (tid >= o) ? sh[tid - o] : 0;
        __syncthreads();
        sh[tid] += t;
        __syncthreads();
    }
    if (i < N) g_row[i] = sh[tid] - v;          // exclusive within block
    if (tid == SCAN_B - 1) g_bsum[blockIdx.x] = sh[tid];

    __threadfence();
    if (tid == 0) flagS = (atomicAdd(&g_scan_ctr, 1) == gridDim.x - 1);
    __syncthreads();
    if (flagS) {
        int bv = (tid < NB) ? g_bsum[tid] : 0;
        sh[tid] = bv;
        __syncthreads();
        #pragma unroll
        for (int o = 1; o < SCAN_B; o <<= 1) {
            int t = (tid >= o) ? sh[tid - o] : 0;
            __syncthreads();
            sh[tid] += t;
            __syncthreads();
        }
        int excl = sh[tid] - bv;
        if (tid < NB) g_bsum[tid] = excl;       // exclusive block offsets
        if (tid == (N >> 9)) g_row[N] = E - excl;  // row_final(N) == E
        if (tid == 0) g_scan_ctr = 0;           // restore invariant for replay
    }
}

// ===========================================================================
// Scatter with fused offset-apply: slot via decrement of g_deg (which also
// restores g_deg==0 for the next launch). Within-node order is irrelevant
// (sum aggregation).
// ===========================================================================
__global__ void scatter_kernel(const int* __restrict__ src,
                               const int* __restrict__ dst, int E)
{
    int e = blockIdx.x * blockDim.x + threadIdx.x;
    if (e < E) {
        int d = dst[e];
        int c = atomicAdd(&g_deg[d], -1) - 1;           // 0..deg-1, deg -> 0
        int p = g_row[d] + g_bsum[d >> 9] + c;
        g_esrc[p] = src[e];
    }
}

// ===========================================================================
// Gather core: 4 dst nodes per warp, 8 lanes per node, fp16 Z rows (64B/node).
// Per inner step: 2 SHFL + 1 LDG.64 + cvt + 4 FMA advance 4 edges.
// Warp-uniform trip count (cntmax over the 4 quarters), padded lanes get w=0.
// ===========================================================================
#define GATHER4_CORE(SScur, SDcur, ZHALF)                                      \
    int lane = threadIdx.x & 31;                                               \
    int l8   = lane & 7;                                                       \
    int qb   = lane & 24;          /* quarter*8 */                             \
    int wrp  = threadIdx.x >> 5;                                               \
    int warpid = blockIdx.x * (blockDim.x >> 5) + wrp;                         \
    int n = warpid * 4 + (lane >> 3);                                          \
    bool valid = (n < N);                                                      \
    int beg = 0, cnt = 0; float sd = 0.f;                                      \
    if (valid) {                                                               \
        beg = g_row[n] + g_bsum[n >> 9];                                       \
        cnt = (g_row[n + 1] + g_bsum[(n + 1) >> 9]) - beg;                     \
        sd  = SDcur[n];                                                        \
    }                                                                          \
    int cntmax = cnt;                                                          \
    cntmax = max(cntmax, __shfl_xor_sync(0xffffffffu, cntmax, 8));             \
    cntmax = max(cntmax, __shfl_xor_sync(0xffffffffu, cntmax, 16));            \
    const uint2* Zv = (const uint2*)ZHALF;                                     \
    float4 acc = make_float4(0.f, 0.f, 0.f, 0.f);                              \
    float den = 0.f;                                                           \
    for (int base = 0; base < cntmax; base += 8) {                             \
        int s = 0; float w = 0.f;                                              \
        if (l8 < cnt - base) {                                                 \
            s = g_esrc[beg + base + l8];                                       \
            float x = SScur[s] + sd;                                           \
            x = (x > 0.f) ? x : 0.01f * x;                                     \
            w = __expf(x);                                                     \
        }                                                                      \
        den += w;                                                              \
        _Pragma("unroll")                                                      \
        for (int t = 0; t < 8; t++) {                                          \
            int b = qb | t;                                                    \
            int st   = __shfl_sync(0xffffffffu, s, b);                         \
            float wt = __shfl_sync(0xffffffffu, w, b);                         \
            uint2 raw = Zv[st * 8 + l8];                                       \
            float2 f0 = __half22float2(*reinterpret_cast<__half2*>(&raw.x));   \
            float2 f1 = __half22float2(*reinterpret_cast<__half2*>(&raw.y));   \
            acc.x = fmaf(wt, f0.x, acc.x);                                     \
            acc.y = fmaf(wt, f0.y, acc.y);                                     \
            acc.z = fmaf(wt, f1.x, acc.z);                                     \
            acc.w = fmaf(wt, f1.y, acc.w);                                     \
        }                                                                      \
    }                                                                          \
    _Pragma("unroll")                                                          \
    for (int o = 4; o; o >>= 1) den += __shfl_xor_sync(0xffffffffu, den, o);   \
    float inv = 1.f / fmaxf(den, 1e-9f);                                       \
    float4 h;                                                                  \
    h.x = fmaxf(acc.x * inv, 0.f);                                             \
    h.y = fmaxf(acc.y * inv, 0.f);                                             \
    h.z = fmaxf(acc.z * inv, 0.f);                                             \
    h.w = fmaxf(acc.w * inv, 0.f);
// h holds relu'd features (4*l8 .. 4*l8+3) of node n.

// ---------------------------------------------------------------------------
// Gather layer 1 + fused layer-2 node GEMM (z2 = h@W2, s_src2, s_dst2).
// ---------------------------------------------------------------------------
__global__ void __launch_bounds__(256)
gather_fuse_L1L2_kernel(int N, const float* __restrict__ W2,
                        const float* __restrict__ a2)
{
    __shared__ float W2s[32 * 32];
    __shared__ float a2s[64];
    int tid0 = threadIdx.x;
    for (int i = tid0; i < 32 * 32; i += blockDim.x) W2s[i] = W2[i];
    if (tid0 < 64) a2s[tid0] = a2[tid0];
    __syncthreads();

    GATHER4_CORE(g_SS1, g_SD1, g_Zh)

    // z2 = h @ W2 ; this lane owns output features 4*l8 .. 4*l8+3
    const float4* W2v = (const float4*)W2s;
    float4 z2 = make_float4(0.f, 0.f, 0.f, 0.f);
    #pragma unroll
    for (int k8 = 0; k8 < 8; k8++) {
        int b = qb | k8;
        float hx = __shfl_sync(0xffffffffu, h.x, b);   // input feature 4*k8
        float hy = __shfl_sync(0xffffffffu, h.y, b);
        float hz = __shfl_sync(0xffffffffu, h.z, b);
        float hv = __shfl_sync(0xffffffffu, h.w, b);
        float4 r0 = W2v[(4 * k8 + 0) * 8 + l8];
        float4 r1 = W2v[(4 * k8 + 1) * 8 + l8];
        float4 r2 = W2v[(4 * k8 + 2) * 8 + l8];
        float4 r3 = W2v[(4 * k8 + 3) * 8 + l8];
        z2.x = fmaf(hx, r0.x, fmaf(hy, r1.x, fmaf(hz, r2.x, fmaf(hv, r3.x, z2.x))));
        z2.y = fmaf(hx, r0.y, fmaf(hy, r1.y, fmaf(hz, r2.y, fmaf(hv, r3.y, z2.y))));
        z2.z = fmaf(hx, r0.z, fmaf(hy, r1.z, fmaf(hz, r2.z, fmaf(hv, r3.z, z2.z))));
        z2.w = fmaf(hx, r0.w, fmaf(hy, r1.w, fmaf(hz, r2.w, fmaf(hv, r3.w, z2.w))));
    }
    float ps = z2.x * a2s[4 * l8]     + z2.y * a2s[4 * l8 + 1]
             + z2.z * a2s[4 * l8 + 2] + z2.w * a2s[4 * l8 + 3];
    float pd = z2.x * a2s[32 + 4 * l8]     + z2.y * a2s[32 + 4 * l8 + 1]
             + z2.z * a2s[32 + 4 * l8 + 2] + z2.w * a2s[32 + 4 * l8 + 3];
    #pragma unroll
    for (int o = 4; o; o >>= 1) {
        ps += __shfl_xor_sync(0xffffffffu, ps, o);
        pd += __shfl_xor_sync(0xffffffffu, pd, o);
    }
    if (valid) {
        __half2 ha = __floats2half2_rn(z2.x, z2.y);
        __half2 hb = __floats2half2_rn(z2.z, z2.w);
        uint2 raw;
        raw.x = *reinterpret_cast<unsigned int*>(&ha);
        raw.y = *reinterpret_cast<unsigned int*>(&hb);
        ((uint2*)g_Z2h)[n * 8 + l8] = raw;
        if (l8 == 0) { g_SS2[n] = ps; g_SD2[n] = pd; }
    }
}

// ---------------------------------------------------------------------------
// Gather layer 2 + fused layer-3 node GEMM (scalar z3 = h.W3, s3 scalars).
// ---------------------------------------------------------------------------
__global__ void __launch_bounds__(256)
gather_fuse_L2L3_kernel(int N, const float* __restrict__ W3,
                        const float* __restrict__ a3)
{
    __shared__ float W3s[32];
    __shared__ float a3s[2];
    int tid0 = threadIdx.x;
    if (tid0 < 32) W3s[tid0] = W3[tid0];
    if (tid0 < 2)  a3s[tid0] = a3[tid0];
    __syncthreads();

    GATHER4_CORE(g_SS2, g_SD2, g_Z2h)

    float z3 = h.x * W3s[4 * l8]     + h.y * W3s[4 * l8 + 1]
             + h.z * W3s[4 * l8 + 2] + h.w * W3s[4 * l8 + 3];
    #pragma unroll
    for (int o = 4; o; o >>= 1) z3 += __shfl_xor_sync(0xffffffffu, z3, o);
    if (valid && l8 == 0) {
        g_Zs[n]  = z3;
        g_SS3[n] = z3 * a3s[0];
        g_SD3[n] = z3 * a3s[1];
    }
}

// ---------------------------------------------------------------------------
// Final gather (dout=1): 4 nodes per warp, normalize + sigmoid -> output.
// ---------------------------------------------------------------------------
__global__ void __launch_bounds__(256)
gather1_kernel(int N, float* __restrict__ out)
{
    int lane = threadIdx.x & 31;
    int l8   = lane & 7;
    int wrp  = threadIdx.x >> 5;
    int warpid = blockIdx.x * (blockDim.x >> 5) + wrp;
    int n = warpid * 4 + (lane >> 3);
    bool valid = (n < N);
    int beg = 0, end = 0; float sd = 0.f;
    if (valid) {
        beg = g_row[n] + g_bsum[n >> 9];
        end = g_row[n + 1] + g_bsum[(n + 1) >> 9];
        sd  = g_SD3[n];
    }

    float acc = 0.f, den = 0.f;
    for (int i = beg + l8; i < end; i += 8) {
        int s = g_esrc[i];
        float x = g_SS3[s] + sd;
        x = (x > 0.f) ? x : 0.01f * x;
        float w = __expf(x);
        den += w;
        acc = fmaf(w, g_Zs[s], acc);
    }
    #pragma unroll
    for (int o = 4; o; o >>= 1) {
        den += __shfl_xor_sync(0xffffffffu, den, o);
        acc += __shfl_xor_sync(0xffffffffu, acc, o);
    }
    if (valid && l8 == 0) {
        float v = acc / fmaxf(den, 1e-9f);
        out[n] = 1.f / (1.f + __expf(-v));
    }
}

// ===========================================================================
extern "C" void kernel_launch(void* const* d_in, const int* in_sizes, int n_in,
                              void* d_out, int out_size)
{
    const float* feat = (const float*)d_in[0];
    const int*   src  = (const int*)d_in[1];
    const int*   dst  = (const int*)d_in[2];
    const float* W1   = (const float*)d_in[3];
    const float* a1   = (const float*)d_in[4];
    const float* W2   = (const float*)d_in[5];
    const float* a2   = (const float*)d_in[6];
    const float* W3   = (const float*)d_in[7];
    const float* a3   = (const float*)d_in[8];

    const int E    = in_sizes[1];
    const int d1   = in_sizes[4] / 2;          // 32
    const int din1 = in_sizes[3] / d1;         // 128
    const int N    = in_sizes[0] / din1;       // 100000

    const int NT  = 256;
    const int WPB = NT / 32;                   // 8 warps/block
    float* out = (float*)d_out;

    // ---- fused dst-histogram + layer-1 node GEMM ----
    const int histBlocks = (E + NT - 1) / NT;
    const int gemmBlocks = (N + 4 * WPB - 1) / (4 * WPB);   // 4 nodes/warp
    {
        size_t shm = (size_t)(din1 * 32 + 64 + WPB * 4 * din1) * sizeof(float);
        hist_gemm_kernel<<<histBlocks + gemmBlocks, NT, shm>>>(
            dst, E, histBlocks, feat, W1, a1, N, din1);
    }

    // ---- CSR scan (decoupled, single kernel) + scatter (fused apply) ----
    const int NB = (N + SCAN_B - 1) / SCAN_B;
    scan1_kernel<<<NB, SCAN_B>>>(N, E, NB);
    scatter_kernel<<<histBlocks, NT>>>(src, dst, E);

    // ---- Gather chains (4 nodes/warp, 8 lanes/node, fp16 Z) ----
    const int quads = (N + 3) / 4;
    const int gBlocks = (quads + WPB - 1) / WPB;
    gather_fuse_L1L2_kernel<<<gBlocks, NT>>>(N, W2, a2);
    gather_fuse_L2L3_kernel<<<gBlocks, NT>>>(N, W3, a3);
    gather1_kernel<<<gBlocks, NT>>>(N, out);
}

// round 12
// speedup vs baseline: 3.4783x; 1.0698x over previous
#include <cuda_runtime.h>
#include <cuda_fp16.h>

// Problem-fixed maxima (from setup_inputs): N=100000, E=1600000, dims 128->32->32->1.
#define MAXN 100000
#define MAXE 1600000
#define SCAN_B 512
#define MAXNB ((MAXN + SCAN_B - 1) / SCAN_B)   // 196

// ---- scratch (device globals; allocation-free per harness rules) ----
// Zero-initialized at module load; every launch restores g_deg==0 and
// g_scan_ctr==0 (scatter decrements deg back to 0; scan1 last block resets ctr),
// so graph replays see identical initial state.
__device__ __half g_Zh[MAXN * 32];   // layer-1 z (fp16 for gather bandwidth)
__device__ __half g_Z2h[MAXN * 32];  // layer-2 z (fp16)
__device__ float g_Zs[MAXN];         // layer-3 z (scalar, fp32)
__device__ float g_SS1[MAXN], g_SD1[MAXN];
__device__ float g_SS2[MAXN], g_SD2[MAXN];
__device__ float g_SS3[MAXN], g_SD3[MAXN];
__device__ int   g_deg[MAXN];        // degree counters (return to 0 each launch)
__device__ int   g_row[MAXN + 1];    // block-local exclusive scan of deg
__device__ int   g_bsum[MAXNB];      // exclusive-scanned block sums
__device__ int   g_esrc[MAXE];       // dst-sorted src ids
__device__ int   g_scan_ctr;         // decoupled-scan counter (self-resetting)

// row_final(i) = g_row[i] + g_bsum[i >> 9]  (valid for 0..N; g_row[N] patched)

// ===========================================================================
// Fused: dst histogram (blocks [0, histBlocks)) + layer-1 node GEMM
// (blocks [histBlocks, ...)). Independent work co-scheduled on the chip.
// GEMM: z = feat@W1 (stored fp16), s_src1/s_dst1. dout=32, 4 nodes per warp.
// ===========================================================================
__global__ void __launch_bounds__(256)
hist_gemm_kernel(const int* __restrict__ dst, int E, int histBlocks,
                 const float* __restrict__ feat,
                 const float* __restrict__ W,
                 const float* __restrict__ a,
                 int N, int din)
{
    if (blockIdx.x < histBlocks) {
        int e = blockIdx.x * blockDim.x + threadIdx.x;
        if (e < E) atomicAdd(&g_deg[dst[e]], 1);
        return;
    }
    int bid = blockIdx.x - histBlocks;

    extern __shared__ float sh[];
    float* Ws = sh;                // din*32
    float* as = Ws + din * 32;     // 64
    float* hs = as + 64;           // WPB * 4 * din

    int tid = threadIdx.x;
    for (int i = tid; i < din * 32; i += blockDim.x) Ws[i] = W[i];
    for (int i = tid; i < 64; i += blockDim.x) as[i] = a[i];
    __syncthreads();

    int lane = tid & 31;
    int wrp  = tid >> 5;
    int WPB  = blockDim.x >> 5;
    float* hw = hs + wrp * 4 * din;

    int n0 = (bid * WPB + wrp) * 4;
    if (n0 >= N) return;
    int cnt = (N - n0 < 4) ? (N - n0) : 4;

    for (int t = 0; t < cnt; t++) {
        const float* hr = feat + (long long)(n0 + t) * din;
        for (int k = lane; k < din; k += 32) hw[t * din + k] = hr[k];
    }
    for (int t = cnt; t < 4; t++)
        for (int k = lane; k < din; k += 32) hw[t * din + k] = 0.f;
    __syncwarp();

    float z0 = 0.f, z1 = 0.f, z2 = 0.f, z3 = 0.f;
    #pragma unroll 8
    for (int k = 0; k < din; k++) {
        float wv = Ws[k * 32 + lane];
        z0 = fmaf(hw[k],           wv, z0);
        z1 = fmaf(hw[din + k],     wv, z1);
        z2 = fmaf(hw[2 * din + k], wv, z2);
        z3 = fmaf(hw[3 * din + k], wv, z3);
    }
    float zz[4] = {z0, z1, z2, z3};
    float aS = as[lane], aD = as[32 + lane];
    for (int t = 0; t < cnt; t++) {
        int n = n0 + t;
        g_Zh[n * 32 + lane] = __float2half(zz[t]);
        float ps = zz[t] * aS, pd = zz[t] * aD;
        #pragma unroll
        for (int o = 16; o; o >>= 1) {
            ps += __shfl_down_sync(0xffffffffu, ps, o);
            pd += __shfl_down_sync(0xffffffffu, pd, o);
        }
        if (lane == 0) { g_SS1[n] = ps; g_SD1[n] = pd; }
    }
}

// ===========================================================================
// scan1: per-block exclusive scan of g_deg into g_row, block totals to g_bsum.
// Decoupled finale: LAST finishing block exclusive-scans g_bsum in place,
// patches g_row[N] so row_final(N)==E, and resets g_scan_ctr for next replay.
// ===========================================================================
__global__ void scan1_kernel(int N, int E, int NB)
{
    __shared__ int sh[SCAN_B];
    __shared__ int flagS;
    int tid = threadIdx.x;
    int i = blockIdx.x * SCAN_B + tid;
    int v = (i < N) ? g_deg[i] : 0;
    sh[tid] = v;
    __syncthreads();
    #pragma unroll
    for (int o = 1; o < SCAN_B; o <<= 1) {
        int t = (tid >= o) ? sh[tid - o] : 0;
        __syncthreads();
        sh[tid] += t;
        __syncthreads();
    }
    if (i < N) g_row[i] = sh[tid] - v;          // exclusive within block
    if (tid == SCAN_B - 1) g_bsum[blockIdx.x] = sh[tid];

    __threadfence();
    if (tid == 0) flagS = (atomicAdd(&g_scan_ctr, 1) == gridDim.x - 1);
    __syncthreads();
    if (flagS) {
        int bv = (tid < NB) ? g_bsum[tid] : 0;
        sh[tid] = bv;
        __syncthreads();
        #pragma unroll
        for (int o = 1; o < SCAN_B; o <<= 1) {
            int t = (tid >= o) ? sh[tid - o] : 0;
            __syncthreads();
            sh[tid] += t;
            __syncthreads();
        }
        int excl = sh[tid] - bv;
        if (tid < NB) g_bsum[tid] = excl;       // exclusive block offsets
        if (tid == (N >> 9)) g_row[N] = E - excl;  // row_final(N) == E
        if (tid == 0) g_scan_ctr = 0;           // restore invariant for replay
    }
}

// ===========================================================================
// Scatter with fused offset-apply: slot via decrement of g_deg (which also
// restores g_deg==0 for the next launch). Within-node order is irrelevant
// (sum aggregation).
// ===========================================================================
__global__ void scatter_kernel(const int* __restrict__ src,
                               const int* __restrict__ dst, int E)
{
    int e = blockIdx.x * blockDim.x + threadIdx.x;
    if (e < E) {
        int d = dst[e];
        int c = atomicAdd(&g_deg[d], -1) - 1;           // 0..deg-1, deg -> 0
        int p = g_row[d] + g_bsum[d >> 9] + c;
        g_esrc[p] = src[e];
    }
}

// ===========================================================================
// Gather core: 8 dst nodes per warp, 4 lanes per node, fp16 Z rows (64B/node),
// NO inner-loop shuffles. All 4 lanes of a group walk the SAME edge: esrc/SS
// loads are same-address (1 request, broadcast), w computed redundantly
// (MUFU is cheap), each lane loads its 16B quarter of the Z row (LDG.128).
// den is group-redundant -> no reduction needed. 2-deep software pipeline.
// After the macro: acc0/acc1 hold 8 features (8*l4 .. 8*l4+7), den valid.
// ===========================================================================
#define FMA8(W, R)                                                             \
    {                                                                          \
        __half2* hp = (__half2*)&(R);                                          \
        float2 f0 = __half22float2(hp[0]);                                     \
        float2 f1 = __half22float2(hp[1]);                                     \
        float2 f2 = __half22float2(hp[2]);                                     \
        float2 f3 = __half22float2(hp[3]);                                     \
        acc0.x = fmaf(W, f0.x, acc0.x); acc0.y = fmaf(W, f0.y, acc0.y);        \
        acc0.z = fmaf(W, f1.x, acc0.z); acc0.w = fmaf(W, f1.y, acc0.w);        \
        acc1.x = fmaf(W, f2.x, acc1.x); acc1.y = fmaf(W, f2.y, acc1.y);        \
        acc1.z = fmaf(W, f3.x, acc1.z); acc1.w = fmaf(W, f3.y, acc1.w);        \
    }

#define GATHER8_CORE(SScur, SDcur, ZHALF)                                      \
    int lane = threadIdx.x & 31;                                               \
    int l4   = lane & 3;                                                       \
    int warpid = blockIdx.x * (blockDim.x >> 5) + (threadIdx.x >> 5);          \
    int n = warpid * 8 + (lane >> 2);                                          \
    bool valid = (n < N);                                                      \
    int beg = 0, cnt = 0; float sd = 0.f;                                      \
    if (valid) {                                                               \
        beg = g_row[n] + g_bsum[n >> 9];                                       \
        cnt = (g_row[n + 1] + g_bsum[(n + 1) >> 9]) - beg;                     \
        sd  = SDcur[n];                                                        \
    }                                                                          \
    const uint4* Zv = (const uint4*)ZHALF;                                     \
    float4 acc0 = make_float4(0.f, 0.f, 0.f, 0.f);                             \
    float4 acc1 = make_float4(0.f, 0.f, 0.f, 0.f);                             \
    float den = 0.f;                                                           \
    int t = 0;                                                                 \
    for (; t + 2 <= cnt; t += 2) {                                             \
        int s0 = g_esrc[beg + t];                                              \
        int s1 = g_esrc[beg + t + 1];                                          \
        float x0 = SScur[s0] + sd;                                             \
        float x1 = SScur[s1] + sd;                                             \
        uint4 r0 = Zv[s0 * 4 + l4];                                            \
        uint4 r1 = Zv[s1 * 4 + l4];                                            \
        x0 = (x0 > 0.f) ? x0 : 0.01f * x0;                                     \
        x1 = (x1 > 0.f) ? x1 : 0.01f * x1;                                     \
        float w0 = __expf(x0);                                                 \
        float w1 = __expf(x1);                                                 \
        den += w0 + w1;                                                        \
        FMA8(w0, r0)                                                           \
        FMA8(w1, r1)                                                           \
    }                                                                          \
    if (t < cnt) {                                                             \
        int s0 = g_esrc[beg + t];                                              \
        float x0 = SScur[s0] + sd;                                             \
        uint4 r0 = Zv[s0 * 4 + l4];                                            \
        x0 = (x0 > 0.f) ? x0 : 0.01f * x0;                                     \
        float w0 = __expf(x0);                                                 \
        den += w0;                                                             \
        FMA8(w0, r0)                                                           \
    }                                                                          \
    float inv = 1.f / fmaxf(den, 1e-9f);                                       \
    float ha[8];                                                               \
    ha[0] = fmaxf(acc0.x * inv, 0.f); ha[1] = fmaxf(acc0.y * inv, 0.f);        \
    ha[2] = fmaxf(acc0.z * inv, 0.f); ha[3] = fmaxf(acc0.w * inv, 0.f);        \
    ha[4] = fmaxf(acc1.x * inv, 0.f); ha[5] = fmaxf(acc1.y * inv, 0.f);        \
    ha[6] = fmaxf(acc1.z * inv, 0.f); ha[7] = fmaxf(acc1.w * inv, 0.f);
// ha holds relu'd features (8*l4 .. 8*l4+7) of node n.

// ---------------------------------------------------------------------------
// Gather layer 1 + fused layer-2 node GEMM (z2 = h@W2, s_src2, s_dst2).
// W2 smem reads are warp-uniform per k (4 distinct addrs), amortized over
// the warp's 8 nodes.
// ---------------------------------------------------------------------------
__global__ void __launch_bounds__(256)
gather_fuse_L1L2_kernel(int N, const float* __restrict__ W2,
                        const float* __restrict__ a2)
{
    __shared__ float W2s[32 * 32];
    __shared__ float a2s[64];
    int tid0 = threadIdx.x;
    for (int i = tid0; i < 32 * 32; i += blockDim.x) W2s[i] = W2[i];
    if (tid0 < 64) a2s[tid0] = a2[tid0];
    __syncthreads();

    GATHER8_CORE(g_SS1, g_SD1, g_Zh)

    // z2[8 outputs: 8*l4 .. 8*l4+7] = sum_k h[k] * W2[k][outputs]
    const float4* W2v = (const float4*)W2s;    // row k = 8 float4s
    float z2[8];
    #pragma unroll
    for (int j = 0; j < 8; j++) z2[j] = 0.f;
    int gbase = lane & 28;                      // first lane of this group
    #pragma unroll
    for (int sl = 0; sl < 4; sl++) {
        #pragma unroll
        for (int i = 0; i < 8; i++) {
            float hk = __shfl_sync(0xffffffffu, ha[i], gbase | sl);
            int k = sl * 8 + i;
            float4 wA = W2v[k * 8 + 2 * l4];
            float4 wB = W2v[k * 8 + 2 * l4 + 1];
            z2[0] = fmaf(hk, wA.x, z2[0]); z2[1] = fmaf(hk, wA.y, z2[1]);
            z2[2] = fmaf(hk, wA.z, z2[2]); z2[3] = fmaf(hk, wA.w, z2[3]);
            z2[4] = fmaf(hk, wB.x, z2[4]); z2[5] = fmaf(hk, wB.y, z2[5]);
            z2[6] = fmaf(hk, wB.z, z2[6]); z2[7] = fmaf(hk, wB.w, z2[7]);
        }
    }
    float ps = 0.f, pd = 0.f;
    #pragma unroll
    for (int j = 0; j < 8; j++) {
        ps = fmaf(z2[j], a2s[8 * l4 + j], ps);
        pd = fmaf(z2[j], a2s[32 + 8 * l4 + j], pd);
    }
    ps += __shfl_xor_sync(0xffffffffu, ps, 1);
    ps += __shfl_xor_sync(0xffffffffu, ps, 2);
    pd += __shfl_xor_sync(0xffffffffu, pd, 1);
    pd += __shfl_xor_sync(0xffffffffu, pd, 2);
    if (valid) {
        __half2 p0 = __floats2half2_rn(z2[0], z2[1]);
        __half2 p1 = __floats2half2_rn(z2[2], z2[3]);
        __half2 p2 = __floats2half2_rn(z2[4], z2[5]);
        __half2 p3 = __floats2half2_rn(z2[6], z2[7]);
        uint4 raw;
        raw.x = *reinterpret_cast<unsigned int*>(&p0);
        raw.y = *reinterpret_cast<unsigned int*>(&p1);
        raw.z = *reinterpret_cast<unsigned int*>(&p2);
        raw.w = *reinterpret_cast<unsigned int*>(&p3);
        ((uint4*)g_Z2h)[n * 4 + l4] = raw;
        if (l4 == 0) { g_SS2[n] = ps; g_SD2[n] = pd; }
    }
}

// ---------------------------------------------------------------------------
// Gather layer 2 + fused layer-3 node GEMM (scalar z3 = h.W3, s3 scalars).
// ---------------------------------------------------------------------------
__global__ void __launch_bounds__(256)
gather_fuse_L2L3_kernel(int N, const float* __restrict__ W3,
                        const float* __restrict__ a3)
{
    __shared__ float W3s[32];
    __shared__ float a3s[2];
    int tid0 = threadIdx.x;
    if (tid0 < 32) W3s[tid0] = W3[tid0];
    if (tid0 < 2)  a3s[tid0] = a3[tid0];
    __syncthreads();

    GATHER8_CORE(g_SS2, g_SD2, g_Z2h)

    float z3 = 0.f;
    #pragma unroll
    for (int i = 0; i < 8; i++) z3 = fmaf(ha[i], W3s[8 * l4 + i], z3);
    z3 += __shfl_xor_sync(0xffffffffu, z3, 1);
    z3 += __shfl_xor_sync(0xffffffffu, z3, 2);
    if (valid && l4 == 0) {
        g_Zs[n]  = z3;
        g_SS3[n] = z3 * a3s[0];
        g_SD3[n] = z3 * a3s[1];
    }
}

// ---------------------------------------------------------------------------
// Final gather (dout=1): 8 nodes/warp, 4 lanes split each node's edges,
// normalize + sigmoid -> output.
// ---------------------------------------------------------------------------
__global__ void __launch_bounds__(256)
gather1_kernel(int N, float* __restrict__ out)
{
    int lane = threadIdx.x & 31;
    int l4   = lane & 3;
    int warpid = blockIdx.x * (blockDim.x >> 5) + (threadIdx.x >> 5);
    int n = warpid * 8 + (lane >> 2);
    bool valid = (n < N);
    int beg = 0, end = 0; float sd = 0.f;
    if (valid) {
        beg = g_row[n] + g_bsum[n >> 9];
        end = g_row[n + 1] + g_bsum[(n + 1) >> 9];
        sd  = g_SD3[n];
    }

    float acc = 0.f, den = 0.f;
    for (int i = beg + l4; i < end; i += 4) {
        int s = g_esrc[i];
        float x = g_SS3[s] + sd;
        x = (x > 0.f) ? x : 0.01f * x;
        float w = __expf(x);
        den += w;
        acc = fmaf(w, g_Zs[s], acc);
    }
    den += __shfl_xor_sync(0xffffffffu, den, 1);
    den += __shfl_xor_sync(0xffffffffu, den, 2);
    acc += __shfl_xor_sync(0xffffffffu, acc, 1);
    acc += __shfl_xor_sync(0xffffffffu, acc, 2);
    if (valid && l4 == 0) {
        float v = acc / fmaxf(den, 1e-9f);
        out[n] = 1.f / (1.f + __expf(-v));
    }
}

// ===========================================================================
extern "C" void kernel_launch(void* const* d_in, const int* in_sizes, int n_in,
                              void* d_out, int out_size)
{
    const float* feat = (const float*)d_in[0];
    const int*   src  = (const int*)d_in[1];
    const int*   dst  = (const int*)d_in[2];
    const float* W1   = (const float*)d_in[3];
    const float* a1   = (const float*)d_in[4];
    const float* W2   = (const float*)d_in[5];
    const float* a2   = (const float*)d_in[6];
    const float* W3   = (const float*)d_in[7];
    const float* a3   = (const float*)d_in[8];

    const int E    = in_sizes[1];
    const int d1   = in_sizes[4] / 2;          // 32
    const int din1 = in_sizes[3] / d1;         // 128
    const int N    = in_sizes[0] / din1;       // 100000

    const int NT  = 256;
    const int WPB = NT / 32;                   // 8 warps/block
    float* out = (float*)d_out;

    // ---- fused dst-histogram + layer-1 node GEMM ----
    const int histBlocks = (E + NT - 1) / NT;
    const int gemmBlocks = (N + 4 * WPB - 1) / (4 * WPB);   // 4 nodes/warp
    {
        size_t shm = (size_t)(din1 * 32 + 64 + WPB * 4 * din1) * sizeof(float);
        hist_gemm_kernel<<<histBlocks + gemmBlocks, NT, shm>>>(
            dst, E, histBlocks, feat, W1, a1, N, din1);
    }

    // ---- CSR scan (decoupled, single kernel) + scatter (fused apply) ----
    const int NB = (N + SCAN_B - 1) / SCAN_B;
    scan1_kernel<<<NB, SCAN_B>>>(N, E, NB);
    scatter_kernel<<<histBlocks, NT>>>(src, dst, E);

    // ---- Gather chains (8 nodes/warp, 4 lanes/node, fp16 Z, no shuffles) ----
    const int octs = (N + 7) / 8;
    const int gBlocks = (octs + WPB - 1) / WPB;
    gather_fuse_L1L2_kernel<<<gBlocks, NT>>>(N, W2, a2);
    gather_fuse_L2L3_kernel<<<gBlocks, NT>>>(N, W3, a3);
    gather1_kernel<<<gBlocks, NT>>>(N, out);
}